// round 1
// baseline (speedup 1.0000x reference)
#include <cuda_runtime.h>
#include <cstddef>

// Problem constants
#define BB 2
#define SS 2048
#define HH 768
#define NHEAD 12
#define HD 64
#define MM (BB*SS)          // 4096
#define SCALE 0.125f        // HD^-0.5

// ---------------------------------------------------------------------------
// Device scratch (static __device__ arrays: allocation-free per harness rules)
// ---------------------------------------------------------------------------
// q/k/v: [n][b][head][s][d]  -> 3*2*12*2048*64 = 9,437,184 floats each (37.7MB)
__device__ float g_q[(size_t)3*BB*NHEAD*SS*HD];
__device__ float g_k[(size_t)3*BB*NHEAD*SS*HD];
__device__ float g_v[(size_t)3*BB*NHEAD*SS*HD];
// scores/probs per n: [b*h][i][j] -> 24*2048*2048 = 100,663,296 floats (402MB each)
__device__ float g_s0[(size_t)BB*NHEAD*SS*SS];
__device__ float g_s1[(size_t)BB*NHEAD*SS*SS];
__device__ float g_s2[(size_t)BB*NHEAD*SS*SS];
// ctx: [n][b][s][H]
__device__ float g_ctx[(size_t)3*BB*SS*HH];

// ---------------------------------------------------------------------------
// Warp reduce helpers
// ---------------------------------------------------------------------------
__device__ __forceinline__ float warpMax(float v){
#pragma unroll
    for(int o=16;o;o>>=1) v = fmaxf(v, __shfl_xor_sync(0xffffffffu, v, o));
    return v;
}
__device__ __forceinline__ float warpSum(float v){
#pragma unroll
    for(int o=16;o;o>>=1) v += __shfl_xor_sync(0xffffffffu, v, o);
    return v;
}

// ---------------------------------------------------------------------------
// K1: QKV projection.  grid = (12, 64, 9)  z -> (type = z/3, n = z%3)
// Y[m,e] = sum_h X[m,h] * W[n][h,e] + b[n][e]
// Output scattered into [n][b][head][s][d] layout.
// ---------------------------------------------------------------------------
__global__ void __launch_bounds__(256) proj_kernel(
    const float* __restrict__ X,
    const float* __restrict__ Wq, const float* __restrict__ bq,
    const float* __restrict__ Wk, const float* __restrict__ bk,
    const float* __restrict__ Wv, const float* __restrict__ bv)
{
    const int z = blockIdx.z;
    const int n = z % 3;
    const int t = z / 3;                 // 0=q, 1=k, 2=v
    const float* W    = (t==0 ? Wq : (t==1 ? Wk : Wv)) + (size_t)n*HH*HH;
    const float* bias = (t==0 ? bq : (t==1 ? bk : bv)) + (size_t)n*HH;
    float* O = (t==0 ? g_q : (t==1 ? g_k : g_v)) + (size_t)n*BB*NHEAD*SS*HD;

    __shared__ float As[16][64];
    __shared__ float Bs[16][64];

    const int tid = threadIdx.x;
    const int tx = tid & 15, ty = tid >> 4;
    const int m0 = blockIdx.y * 64;
    const int e0 = blockIdx.x * 64;
    const int head = blockIdx.x;         // H=768 = 12 heads * 64

    float acc[4][4] = {};

    for(int k0 = 0; k0 < HH; k0 += 16){
        {   // A tile: X[m0..+64][k0..+16], store transposed As[k][m]
            int r  = tid >> 2;
            int c4 = (tid & 3) << 2;
            float4 v = *(const float4*)(X + (size_t)(m0 + r)*HH + k0 + c4);
            As[c4+0][r]=v.x; As[c4+1][r]=v.y; As[c4+2][r]=v.z; As[c4+3][r]=v.w;
        }
        {   // B tile: W[k0..+16][e0..+64], store as Bs[k][e]
            int r  = tid >> 4;
            int c4 = (tid & 15) << 2;
            *(float4*)&Bs[r][c4] = *(const float4*)(W + (size_t)(k0 + r)*HH + e0 + c4);
        }
        __syncthreads();
#pragma unroll
        for(int kk=0; kk<16; kk++){
            float4 af = *(const float4*)&As[kk][ty*4];
            float4 bf = *(const float4*)&Bs[kk][tx*4];
            float av[4] = {af.x, af.y, af.z, af.w};
            float bv4[4] = {bf.x, bf.y, bf.z, bf.w};
#pragma unroll
            for(int ii=0; ii<4; ii++)
#pragma unroll
                for(int jj=0; jj<4; jj++)
                    acc[ii][jj] = fmaf(av[ii], bv4[jj], acc[ii][jj]);
        }
        __syncthreads();
    }

    const int d = tx * 4;
#pragma unroll
    for(int ii=0; ii<4; ii++){
        int m = m0 + ty*4 + ii;
        int b = m >> 11;           // /SS
        int s = m & (SS-1);
        float4 o;
        o.x = acc[ii][0] + bias[e0 + d + 0];
        o.y = acc[ii][1] + bias[e0 + d + 1];
        o.z = acc[ii][2] + bias[e0 + d + 2];
        o.w = acc[ii][3] + bias[e0 + d + 3];
        float* dst = O + (((size_t)b*NHEAD + head)*SS + s)*HD + d;
        *(float4*)dst = o;
    }
}

// ---------------------------------------------------------------------------
// K2: scores.  grid = (32, 32, 72)  z -> n = z/24, bh = z%24
// s[i][j] = SCALE * sum_d q[i][d]*k[j][d]   (+ mask -> -1e30)
// ---------------------------------------------------------------------------
__global__ void __launch_bounds__(256) score_kernel(const int* __restrict__ mask)
{
    const int z  = blockIdx.z;
    const int n  = z / 24;
    const int bh = z % 24;
    const int b  = bh / NHEAD;

    const float* q = g_q + ((size_t)n*BB*NHEAD + bh)*SS*HD;
    const float* k = g_k + ((size_t)n*BB*NHEAD + bh)*SS*HD;
    float* sout = (n==0 ? g_s0 : (n==1 ? g_s1 : g_s2)) + (size_t)bh*SS*SS;

    __shared__ float Qs[64][64];   // [d][i]
    __shared__ float Ks[64][64];   // [d][j]

    const int tid = threadIdx.x;
    const int tx = tid & 15, ty = tid >> 4;
    const int i0 = blockIdx.y * 64;
    const int j0 = blockIdx.x * 64;

#pragma unroll
    for(int rep=0; rep<4; rep++){
        int idx = rep*256 + tid;
        int r   = idx >> 4;
        int c4  = (idx & 15) << 2;
        float4 v = *(const float4*)(q + (size_t)(i0 + r)*HD + c4);
        Qs[c4+0][r]=v.x; Qs[c4+1][r]=v.y; Qs[c4+2][r]=v.z; Qs[c4+3][r]=v.w;
        float4 w = *(const float4*)(k + (size_t)(j0 + r)*HD + c4);
        Ks[c4+0][r]=w.x; Ks[c4+1][r]=w.y; Ks[c4+2][r]=w.z; Ks[c4+3][r]=w.w;
    }
    __syncthreads();

    float acc[4][4] = {};
#pragma unroll 16
    for(int d=0; d<64; d++){
        float4 af = *(const float4*)&Qs[d][ty*4];
        float4 bf = *(const float4*)&Ks[d][tx*4];
        float av[4] = {af.x, af.y, af.z, af.w};
        float bv4[4] = {bf.x, bf.y, bf.z, bf.w};
#pragma unroll
        for(int ii=0; ii<4; ii++)
#pragma unroll
            for(int jj=0; jj<4; jj++)
                acc[ii][jj] = fmaf(av[ii], bv4[jj], acc[ii][jj]);
    }

#pragma unroll
    for(int ii=0; ii<4; ii++){
        int i = i0 + ty*4 + ii;
        float4 o;
        float* op = (float*)&o;
#pragma unroll
        for(int jj=0; jj<4; jj++){
            int j = j0 + tx*4 + jj;
            float v = acc[ii][jj] * SCALE;
            if(mask[b*SS + j] == 0) v = -1e30f;
            op[jj] = v;
        }
        *(float4*)(sout + (size_t)i*SS + j0 + tx*4) = o;
    }
}

// ---------------------------------------------------------------------------
// K3: row softmax for s0, s1 (in place).  grid = (49152, 2), 256 threads.
// (query-position biases cancel in softmax, so they are omitted)
// ---------------------------------------------------------------------------
__global__ void __launch_bounds__(256) softmax01_kernel()
{
    const int n = blockIdx.y;
    float* p = (n ? g_s1 : g_s0) + (size_t)blockIdx.x * SS;
    const int tid = threadIdx.x;

    float v[8];
    float4 a = *(const float4*)(p + tid*8);
    float4 c = *(const float4*)(p + tid*8 + 4);
    v[0]=a.x; v[1]=a.y; v[2]=a.z; v[3]=a.w;
    v[4]=c.x; v[5]=c.y; v[6]=c.z; v[7]=c.w;

    __shared__ float sred[8];
    __shared__ float sbc;

    float m = v[0];
#pragma unroll
    for(int i=1;i<8;i++) m = fmaxf(m, v[i]);
    m = warpMax(m);
    if((tid&31)==0) sred[tid>>5] = m;
    __syncthreads();
    if(tid==0){ float x=sred[0]; for(int i=1;i<8;i++) x=fmaxf(x,sred[i]); sbc=x; }
    __syncthreads();
    const float rowm = sbc;

    float ls = 0.f;
#pragma unroll
    for(int i=0;i<8;i++){ v[i] = expf(v[i] - rowm); ls += v[i]; }
    ls = warpSum(ls);
    __syncthreads();
    if((tid&31)==0) sred[tid>>5] = ls;
    __syncthreads();
    if(tid==0){ float x=0; for(int i=0;i<8;i++) x+=sred[i]; sbc = 1.0f/x; }
    __syncthreads();
    const float inv = sbc;

    float4 o1, o2;
    o1.x=v[0]*inv; o1.y=v[1]*inv; o1.z=v[2]*inv; o1.w=v[3]*inv;
    o2.x=v[4]*inv; o2.y=v[5]*inv; o2.z=v[6]*inv; o2.w=v[7]*inv;
    *(float4*)(p + tid*8)     = o1;
    *(float4*)(p + tid*8 + 4) = o2;
}

// ---------------------------------------------------------------------------
// K4: p_c = softmax(s2 + 0.5*(p_a + p_o)) in place over g_s2. grid = 49152.
// ---------------------------------------------------------------------------
__global__ void __launch_bounds__(256) softmaxc_kernel()
{
    const size_t row = (size_t)blockIdx.x * SS;
    const float* pa = g_s0 + row;
    const float* po = g_s1 + row;
    float* p2 = g_s2 + row;
    const int tid = threadIdx.x;

    float v[8];
#pragma unroll
    for(int h=0; h<2; h++){
        float4 a = *(const float4*)(p2 + tid*8 + h*4);
        float4 x = *(const float4*)(pa + tid*8 + h*4);
        float4 y = *(const float4*)(po + tid*8 + h*4);
        v[h*4+0] = a.x + 0.5f*(x.x + y.x);
        v[h*4+1] = a.y + 0.5f*(x.y + y.y);
        v[h*4+2] = a.z + 0.5f*(x.z + y.z);
        v[h*4+3] = a.w + 0.5f*(x.w + y.w);
    }

    __shared__ float sred[8];
    __shared__ float sbc;

    float m = v[0];
#pragma unroll
    for(int i=1;i<8;i++) m = fmaxf(m, v[i]);
    m = warpMax(m);
    if((tid&31)==0) sred[tid>>5] = m;
    __syncthreads();
    if(tid==0){ float x=sred[0]; for(int i=1;i<8;i++) x=fmaxf(x,sred[i]); sbc=x; }
    __syncthreads();
    const float rowm = sbc;

    float ls = 0.f;
#pragma unroll
    for(int i=0;i<8;i++){ v[i] = expf(v[i] - rowm); ls += v[i]; }
    ls = warpSum(ls);
    __syncthreads();
    if((tid&31)==0) sred[tid>>5] = ls;
    __syncthreads();
    if(tid==0){ float x=0; for(int i=0;i<8;i++) x+=sred[i]; sbc = 1.0f/x; }
    __syncthreads();
    const float inv = sbc;

    float4 o1, o2;
    o1.x=v[0]*inv; o1.y=v[1]*inv; o1.z=v[2]*inv; o1.w=v[3]*inv;
    o2.x=v[4]*inv; o2.y=v[5]*inv; o2.z=v[6]*inv; o2.w=v[7]*inv;
    *(float4*)(p2 + tid*8)     = o1;
    *(float4*)(p2 + tid*8 + 4) = o2;
}

// ---------------------------------------------------------------------------
// K5: ctx = P @ V.  grid = (32, 72).  M=2048, N=64, K=2048, BK=32.
// Output into g_ctx [n][b][s][head*64+d]
// ---------------------------------------------------------------------------
__global__ void __launch_bounds__(256) ctx_kernel()
{
    const int z  = blockIdx.y;
    const int n  = z / 24;
    const int bh = z % 24;
    const int b  = bh / NHEAD;
    const int h  = bh % NHEAD;

    const float* p = (n==0 ? g_s0 : (n==1 ? g_s1 : g_s2)) + (size_t)bh*SS*SS;
    const float* vv = g_v + ((size_t)n*BB*NHEAD + bh)*SS*HD;
    const int i0 = blockIdx.x * 64;

    __shared__ float Ps[32][64];  // [j][i]
    __shared__ float Vs[32][64];  // [j][d]

    const int tid = threadIdx.x;
    const int tx = tid & 15, ty = tid >> 4;

    float acc[4][4] = {};

    for(int j0 = 0; j0 < SS; j0 += 32){
#pragma unroll
        for(int rep=0; rep<2; rep++){
            int idx = rep*256 + tid;
            {   // P tile [64 i][32 j] -> Ps[j][i]
                int r  = idx >> 3;
                int c4 = (idx & 7) << 2;
                float4 t = *(const float4*)(p + (size_t)(i0 + r)*SS + j0 + c4);
                Ps[c4+0][r]=t.x; Ps[c4+1][r]=t.y; Ps[c4+2][r]=t.z; Ps[c4+3][r]=t.w;
            }
            {   // V tile [32 j][64 d] -> Vs[j][d]
                int r  = idx >> 4;
                int c4 = (idx & 15) << 2;
                *(float4*)&Vs[r][c4] = *(const float4*)(vv + (size_t)(j0 + r)*HD + c4);
            }
        }
        __syncthreads();
#pragma unroll
        for(int j=0; j<32; j++){
            float4 af = *(const float4*)&Ps[j][ty*4];
            float4 bf = *(const float4*)&Vs[j][tx*4];
            float av[4] = {af.x, af.y, af.z, af.w};
            float bv4[4] = {bf.x, bf.y, bf.z, bf.w};
#pragma unroll
            for(int ii=0; ii<4; ii++)
#pragma unroll
                for(int jj=0; jj<4; jj++)
                    acc[ii][jj] = fmaf(av[ii], bv4[jj], acc[ii][jj]);
        }
        __syncthreads();
    }

#pragma unroll
    for(int ii=0; ii<4; ii++){
        int i = i0 + ty*4 + ii;
        float4 o;
        o.x=acc[ii][0]; o.y=acc[ii][1]; o.z=acc[ii][2]; o.w=acc[ii][3];
        float* dst = g_ctx + (((size_t)n*BB + b)*SS + i)*HH + h*HD + tx*4;
        *(float4*)dst = o;
    }
}

// ---------------------------------------------------------------------------
// K6: output projection.  grid = (12, 64, 3).
// out[n][m][e] = sum_h ctx[n][m][h] * Wo[n][h][e] + bo[n][e]
// ---------------------------------------------------------------------------
__global__ void __launch_bounds__(256) outproj_kernel(
    const float* __restrict__ Wo, const float* __restrict__ bo,
    float* __restrict__ out)
{
    const int n = blockIdx.z;
    const float* X    = g_ctx + (size_t)n*MM*HH;
    const float* W    = Wo + (size_t)n*HH*HH;
    const float* bias = bo + (size_t)n*HH;
    float* O = out + (size_t)n*MM*HH;

    __shared__ float As[16][64];
    __shared__ float Bs[16][64];

    const int tid = threadIdx.x;
    const int tx = tid & 15, ty = tid >> 4;
    const int m0 = blockIdx.y * 64;
    const int e0 = blockIdx.x * 64;

    float acc[4][4] = {};

    for(int k0 = 0; k0 < HH; k0 += 16){
        {
            int r  = tid >> 2;
            int c4 = (tid & 3) << 2;
            float4 v = *(const float4*)(X + (size_t)(m0 + r)*HH + k0 + c4);
            As[c4+0][r]=v.x; As[c4+1][r]=v.y; As[c4+2][r]=v.z; As[c4+3][r]=v.w;
        }
        {
            int r  = tid >> 4;
            int c4 = (tid & 15) << 2;
            *(float4*)&Bs[r][c4] = *(const float4*)(W + (size_t)(k0 + r)*HH + e0 + c4);
        }
        __syncthreads();
#pragma unroll
        for(int kk=0; kk<16; kk++){
            float4 af = *(const float4*)&As[kk][ty*4];
            float4 bf = *(const float4*)&Bs[kk][tx*4];
            float av[4] = {af.x, af.y, af.z, af.w};
            float bv4[4] = {bf.x, bf.y, bf.z, bf.w};
#pragma unroll
            for(int ii=0; ii<4; ii++)
#pragma unroll
                for(int jj=0; jj<4; jj++)
                    acc[ii][jj] = fmaf(av[ii], bv4[jj], acc[ii][jj]);
        }
        __syncthreads();
    }

    const int e = e0 + tx*4;
#pragma unroll
    for(int ii=0; ii<4; ii++){
        int m = m0 + ty*4 + ii;
        float4 o;
        o.x = acc[ii][0] + bias[e + 0];
        o.y = acc[ii][1] + bias[e + 1];
        o.z = acc[ii][2] + bias[e + 2];
        o.w = acc[ii][3] + bias[e + 3];
        *(float4*)(O + (size_t)m*HH + e) = o;
    }
}

// ---------------------------------------------------------------------------
// Launch
// ---------------------------------------------------------------------------
extern "C" void kernel_launch(void* const* d_in, const int* in_sizes, int n_in,
                              void* d_out, int out_size)
{
    (void)in_sizes; (void)n_in; (void)out_size;
    const float* hidden = (const float*)d_in[0];
    // d_in[1] aspect_weights, d_in[2] opinion_weights: cancel in softmax (per-query-row bias)
    const int*   mask   = (const int*)  d_in[3];
    const float* Wq = (const float*)d_in[4];  const float* bq = (const float*)d_in[5];
    const float* Wk = (const float*)d_in[6];  const float* bk = (const float*)d_in[7];
    const float* Wv = (const float*)d_in[8];  const float* bv = (const float*)d_in[9];
    const float* Wo = (const float*)d_in[10]; const float* bo = (const float*)d_in[11];
    float* out = (float*)d_out;

    proj_kernel<<<dim3(12, 64, 9), 256>>>(hidden, Wq, bq, Wk, bk, Wv, bv);
    score_kernel<<<dim3(32, 32, 72), 256>>>(mask);
    softmax01_kernel<<<dim3(BB*NHEAD*SS, 2), 256>>>();
    softmaxc_kernel<<<dim3(BB*NHEAD*SS), 256>>>();
    ctx_kernel<<<dim3(32, 72), 256>>>();
    outproj_kernel<<<dim3(12, 64, 3), 256>>>(Wo, bo, out);
}

// round 2
// speedup vs baseline: 2.6949x; 2.6949x over previous
#include <cuda_runtime.h>
#include <cstddef>

// Problem constants
#define BB 2
#define SS 2048
#define HH 768
#define NHEAD 12
#define HD 64
#define MM (BB*SS)          // 4096
#define SCALE 0.125f        // HD^-0.5

// ---------------------------------------------------------------------------
// Device scratch
// ---------------------------------------------------------------------------
__device__ float g_q [(size_t)3*BB*NHEAD*SS*HD];
__device__ float g_k [(size_t)3*BB*NHEAD*SS*HD];
__device__ float g_v [(size_t)3*BB*NHEAD*SS*HD];
__device__ float g_vt[(size_t)3*BB*NHEAD*SS*HD];     // V transposed: [n][bh][d][s]
__device__ float g_s0[(size_t)BB*NHEAD*SS*SS];
__device__ float g_s1[(size_t)BB*NHEAD*SS*SS];
__device__ float g_s2[(size_t)BB*NHEAD*SS*SS];
__device__ float g_ctx[(size_t)3*MM*HH];
__device__ float g_wt[(size_t)12*HH*HH];             // transposed weights: q0..2,k0..2,v0..2,o0..2

// ---------------------------------------------------------------------------
// tf32 mma helpers
// ---------------------------------------------------------------------------
__device__ __forceinline__ unsigned f2tf(float x){
    unsigned r; asm("cvt.rna.tf32.f32 %0, %1;" : "=r"(r) : "f"(x)); return r;
}
__device__ __forceinline__ void mma8(float c[4], const unsigned a[4], const unsigned b[2]){
    asm volatile("mma.sync.aligned.m16n8k8.row.col.f32.tf32.tf32.f32 "
        "{%0,%1,%2,%3},{%4,%5,%6,%7},{%8,%9},{%0,%1,%2,%3};"
        : "+f"(c[0]),"+f"(c[1]),"+f"(c[2]),"+f"(c[3])
        : "r"(a[0]),"r"(a[1]),"r"(a[2]),"r"(a[3]),"r"(b[0]),"r"(b[1]));
}
// smem layout: rows of exactly 32 floats (=BK), float4-group XOR swizzle.
// float-index of 4-group start for (row, group c):
__device__ __forceinline__ int swz(int row, int c){ return (row<<5) + (((c ^ (row & 7)))<<2); }

// Load a [ROWS x 32] k-major tile from gmem (row stride ld) into swizzled smem (tf32).
template<int ROWS>
__device__ __forceinline__ void load_tile(unsigned* s, const float* __restrict__ g,
                                          size_t ld, int k0, int tid){
#pragma unroll
    for(int i=0;i<ROWS*8/256;i++){
        int idx = i*256 + tid;
        int row = idx>>3, c = idx&7;
        float4 v = *(const float4*)(g + (size_t)row*ld + k0 + 4*c);
        uint4 u; u.x=f2tf(v.x); u.y=f2tf(v.y); u.z=f2tf(v.z); u.w=f2tf(v.w);
        *(uint4*)(s + swz(row,c)) = u;
    }
}

// One BK=32 block-step of mma for a warp tile of MI m16-tiles x NI n8-tiles.
template<int MI,int NI>
__device__ __forceinline__ void mma_block(const unsigned* sA, const unsigned* sB,
        int wm_base, int wn_base, int gid, int tig, float acc[MI][NI][4]){
#pragma unroll
    for(int ks=0;ks<4;ks++){
        unsigned af[MI][4], bf[NI][2];
#pragma unroll
        for(int mi=0;mi<MI;mi++){
            int m = wm_base + mi*16 + gid;
            af[mi][0] = sA[swz(m,   2*ks  )+tig];
            af[mi][1] = sA[swz(m+8, 2*ks  )+tig];
            af[mi][2] = sA[swz(m,   2*ks+1)+tig];
            af[mi][3] = sA[swz(m+8, 2*ks+1)+tig];
        }
#pragma unroll
        for(int ni=0;ni<NI;ni++){
            int n = wn_base + ni*8 + gid;
            bf[ni][0] = sB[swz(n, 2*ks  )+tig];
            bf[ni][1] = sB[swz(n, 2*ks+1)+tig];
        }
#pragma unroll
        for(int mi=0;mi<MI;mi++)
#pragma unroll
            for(int ni=0;ni<NI;ni++)
                mma8(acc[mi][ni], af[mi], bf[ni]);
    }
}

// ---------------------------------------------------------------------------
// K0a: transpose the 12 weight matrices [h][e] -> g_wt[mat][e][h]
// ---------------------------------------------------------------------------
__global__ void __launch_bounds__(256) transpose_w(
    const float* __restrict__ Wq, const float* __restrict__ Wk,
    const float* __restrict__ Wv, const float* __restrict__ Wo)
{
    __shared__ float t[32][33];
    const int mat = blockIdx.z;
    const float* src = (mat<3?Wq:mat<6?Wk:mat<9?Wv:Wo) + (size_t)(mat%3)*HH*HH;
    float* dst = g_wt + (size_t)mat*HH*HH;
    const int x0 = blockIdx.x*32, y0 = blockIdx.y*32;
    const int tx = threadIdx.x & 31, ty = threadIdx.x >> 5;  // 32 x 8
#pragma unroll
    for(int r=0;r<4;r++) t[ty+8*r][tx] = src[(size_t)(y0+ty+8*r)*HH + x0 + tx];
    __syncthreads();
#pragma unroll
    for(int r=0;r<4;r++) dst[(size_t)(x0+ty+8*r)*HH + y0 + tx] = t[tx][ty+8*r];
}

// K1b: transpose V per head: [s][d] -> [d][s]
__global__ void __launch_bounds__(256) transpose_v()
{
    __shared__ float t[32][33];
    const int z = blockIdx.z;                   // n*24+bh
    const float* src = g_v  + (size_t)z*SS*HD;
    float* dst       = g_vt + (size_t)z*SS*HD;
    const int d0 = blockIdx.x*32, s0 = blockIdx.y*32;
    const int tx = threadIdx.x & 31, ty = threadIdx.x >> 5;
#pragma unroll
    for(int r=0;r<4;r++) t[ty+8*r][tx] = src[(size_t)(s0+ty+8*r)*HD + d0 + tx];
    __syncthreads();
#pragma unroll
    for(int r=0;r<4;r++) dst[(size_t)(d0+ty+8*r)*SS + s0 + tx] = t[tx][ty+8*r];
}

// ---------------------------------------------------------------------------
// K1: QKV projection (tf32).  grid (6, 32, 9): x=e-tile/128, y=m-tile/128, z=(t*3+n)
// ---------------------------------------------------------------------------
__global__ void __launch_bounds__(256) proj_tc(
    const float* __restrict__ X,
    const float* __restrict__ bq, const float* __restrict__ bk, const float* __restrict__ bv)
{
    __shared__ unsigned sA[128*32], sB[128*32];
    const int z = blockIdx.z, n = z%3, t = z/3;
    const float* Wt   = g_wt + (size_t)(t*3+n)*HH*HH;
    const float* bias = (t==0?bq:(t==1?bk:bv)) + (size_t)n*HH;
    float* O = (t==0?g_q:(t==1?g_k:g_v)) + (size_t)n*BB*NHEAD*SS*HD;

    const int m0 = blockIdx.y*128, e0 = blockIdx.x*128;
    const int tid = threadIdx.x, wid = tid>>5, lane = tid&31;
    const int gid = lane>>2, tig = lane&3;
    const int wm = wid & 1, wn = wid >> 1;       // 2x4, warp tile 64x32

    float acc[4][4][4] = {};
    for(int k0=0;k0<HH;k0+=32){
        load_tile<128>(sA, X  + (size_t)m0*HH, HH, k0, tid);
        load_tile<128>(sB, Wt + (size_t)e0*HH, HH, k0, tid);
        __syncthreads();
        mma_block<4,4>(sA, sB, wm*64, wn*32, gid, tig, acc);
        __syncthreads();
    }
#pragma unroll
    for(int mi=0;mi<4;mi++)
#pragma unroll
    for(int ni=0;ni<4;ni++){
        const int e = e0 + wn*32 + ni*8 + 2*tig;
        const float2 b2 = *(const float2*)(bias + e);
        const int head = e>>6, d = e&63;
#pragma unroll
        for(int h2=0;h2<2;h2++){
            int m = m0 + wm*64 + mi*16 + gid + h2*8;
            int b = m>>11, s = m & (SS-1);
            float2 o; o.x = acc[mi][ni][h2*2+0] + b2.x; o.y = acc[mi][ni][h2*2+1] + b2.y;
            *(float2*)(O + (((size_t)b*NHEAD + head)*SS + s)*HD + d) = o;
        }
    }
}

// ---------------------------------------------------------------------------
// K2: scores (tf32).  grid (16, 16, 72): z -> n = z/24, bh = z%24
// ---------------------------------------------------------------------------
__global__ void __launch_bounds__(256) score_tc(const int* __restrict__ mask)
{
    __shared__ unsigned sA[128*32], sB[128*32];
    const int z = blockIdx.z, n = z/24, bh = z%24, b = bh/NHEAD;
    const float* q = g_q + ((size_t)n*24 + bh)*SS*HD;
    const float* k = g_k + ((size_t)n*24 + bh)*SS*HD;
    float* sout = (n==0?g_s0:(n==1?g_s1:g_s2)) + (size_t)bh*SS*SS;

    const int i0 = blockIdx.y*128, j0 = blockIdx.x*128;
    const int tid = threadIdx.x, wid = tid>>5, lane = tid&31;
    const int gid = lane>>2, tig = lane&3;
    const int wm = wid & 1, wn = wid >> 1;

    float acc[4][4][4] = {};
#pragma unroll
    for(int k0=0;k0<HD;k0+=32){
        load_tile<128>(sA, q + (size_t)i0*HD, HD, k0, tid);
        load_tile<128>(sB, k + (size_t)j0*HD, HD, k0, tid);
        __syncthreads();
        mma_block<4,4>(sA, sB, wm*64, wn*32, gid, tig, acc);
        __syncthreads();
    }
#pragma unroll
    for(int mi=0;mi<4;mi++)
#pragma unroll
    for(int ni=0;ni<4;ni++){
        const int j = j0 + wn*32 + ni*8 + 2*tig;
        const bool mk0 = (mask[b*SS + j    ] == 0);
        const bool mk1 = (mask[b*SS + j + 1] == 0);
#pragma unroll
        for(int h2=0;h2<2;h2++){
            int i = i0 + wm*64 + mi*16 + gid + h2*8;
            float2 o;
            o.x = mk0 ? -1e30f : acc[mi][ni][h2*2+0]*SCALE;
            o.y = mk1 ? -1e30f : acc[mi][ni][h2*2+1]*SCALE;
            *(float2*)(sout + (size_t)i*SS + j) = o;
        }
    }
}

// ---------------------------------------------------------------------------
// K3: merged softmax. p_a=softmax(s0), p_o=softmax(s1), p_c=softmax(s2+0.5(p_a+p_o))
// grid 49152, 256 threads, 8 elems/thread. (query-row biases cancel -> omitted)
// ---------------------------------------------------------------------------
__device__ __forceinline__ float warpMax(float v){
#pragma unroll
    for(int o=16;o;o>>=1) v = fmaxf(v, __shfl_xor_sync(0xffffffffu, v, o));
    return v;
}
__device__ __forceinline__ float warpSum(float v){
#pragma unroll
    for(int o=16;o;o>>=1) v += __shfl_xor_sync(0xffffffffu, v, o);
    return v;
}

__global__ void __launch_bounds__(256) softmax_all()
{
    const size_t row = (size_t)blockIdx.x * SS;
    float* p0 = g_s0 + row;
    float* p1 = g_s1 + row;
    float* p2 = g_s2 + row;
    const int tid = threadIdx.x, lane = tid&31, warp = tid>>5;

    float v0[8], v1[8], v2[8];
    *(float4*)(v0  ) = *(const float4*)(p0 + tid*8);
    *(float4*)(v0+4) = *(const float4*)(p0 + tid*8 + 4);
    *(float4*)(v1  ) = *(const float4*)(p1 + tid*8);
    *(float4*)(v1+4) = *(const float4*)(p1 + tid*8 + 4);
    *(float4*)(v2  ) = *(const float4*)(p2 + tid*8);
    *(float4*)(v2+4) = *(const float4*)(p2 + tid*8 + 4);

    __shared__ float rA[8], rB[8];
    __shared__ float bA, bB;

    // max of s0, s1
    float m0 = v0[0], m1 = v1[0];
#pragma unroll
    for(int i=1;i<8;i++){ m0 = fmaxf(m0, v0[i]); m1 = fmaxf(m1, v1[i]); }
    m0 = warpMax(m0); m1 = warpMax(m1);
    if(lane==0){ rA[warp]=m0; rB[warp]=m1; }
    __syncthreads();
    if(tid==0){ float a=rA[0], c=rB[0];
        for(int i=1;i<8;i++){ a=fmaxf(a,rA[i]); c=fmaxf(c,rB[i]); } bA=a; bB=c; }
    __syncthreads();
    const float M0=bA, M1=bB;

    // sums
    float s0=0.f, s1=0.f;
#pragma unroll
    for(int i=0;i<8;i++){ v0[i]=__expf(v0[i]-M0); s0+=v0[i];
                          v1[i]=__expf(v1[i]-M1); s1+=v1[i]; }
    s0 = warpSum(s0); s1 = warpSum(s1);
    if(lane==0){ rA[warp]=s0; rB[warp]=s1; }
    __syncthreads();
    if(tid==0){ float a=0,c=0; for(int i=0;i<8;i++){a+=rA[i]; c+=rB[i];}
        bA=1.0f/a; bB=1.0f/c; }
    __syncthreads();
    const float inv0=bA, inv1=bB;

    float t[8];
#pragma unroll
    for(int i=0;i<8;i++){
        v0[i] *= inv0; v1[i] *= inv1;
        t[i] = v2[i] + 0.5f*(v0[i] + v1[i]);
    }
    *(float4*)(p0 + tid*8    ) = *(float4*)(v0  );
    *(float4*)(p0 + tid*8 + 4) = *(float4*)(v0+4);
    *(float4*)(p1 + tid*8    ) = *(float4*)(v1  );
    *(float4*)(p1 + tid*8 + 4) = *(float4*)(v1+4);

    // softmax over t
    float m2 = t[0];
#pragma unroll
    for(int i=1;i<8;i++) m2 = fmaxf(m2, t[i]);
    m2 = warpMax(m2);
    if(lane==0) rA[warp]=m2;
    __syncthreads();
    if(tid==0){ float a=rA[0]; for(int i=1;i<8;i++) a=fmaxf(a,rA[i]); bA=a; }
    __syncthreads();
    const float M2=bA;

    float s2=0.f;
#pragma unroll
    for(int i=0;i<8;i++){ t[i]=__expf(t[i]-M2); s2+=t[i]; }
    s2 = warpSum(s2);
    __syncthreads();
    if(lane==0) rA[warp]=s2;
    __syncthreads();
    if(tid==0){ float a=0; for(int i=0;i<8;i++) a+=rA[i]; bA=1.0f/a; }
    __syncthreads();
    const float inv2=bA;
#pragma unroll
    for(int i=0;i<8;i++) t[i]*=inv2;
    *(float4*)(p2 + tid*8    ) = *(float4*)(t  );
    *(float4*)(p2 + tid*8 + 4) = *(float4*)(t+4);
}

// ---------------------------------------------------------------------------
// K4: ctx = P @ V (tf32).  grid (16, 72). BM=128 (i), BN=64 (d), K=2048.
// A = P (k-contig), B = g_vt [d][s] (k-contig). warps 4x2, warp tile 32x32.
// ---------------------------------------------------------------------------
__global__ void __launch_bounds__(256) ctx_tc()
{
    __shared__ unsigned sA[128*32], sB[64*32];
    const int z = blockIdx.y, n = z/24, bh = z%24, b = bh/NHEAD, h = bh%NHEAD;
    const float* P  = (n==0?g_s0:(n==1?g_s1:g_s2)) + (size_t)bh*SS*SS;
    const float* Vt = g_vt + ((size_t)n*24 + bh)*SS*HD;
    const int i0 = blockIdx.x*128;

    const int tid = threadIdx.x, wid = tid>>5, lane = tid&31;
    const int gid = lane>>2, tig = lane&3;
    const int wm = wid & 3, wn = wid >> 2;   // 4x2

    float acc[2][4][4] = {};
    for(int k0=0;k0<SS;k0+=32){
        load_tile<128>(sA, P + (size_t)i0*SS, SS, k0, tid);
        load_tile<64 >(sB, Vt,                SS, k0, tid);
        __syncthreads();
        mma_block<2,4>(sA, sB, wm*32, wn*32, gid, tig, acc);
        __syncthreads();
    }
#pragma unroll
    for(int mi=0;mi<2;mi++)
#pragma unroll
    for(int ni=0;ni<4;ni++){
        const int d = wn*32 + ni*8 + 2*tig;
#pragma unroll
        for(int h2=0;h2<2;h2++){
            int i = i0 + wm*32 + mi*16 + gid + h2*8;
            float2 o; o.x = acc[mi][ni][h2*2+0]; o.y = acc[mi][ni][h2*2+1];
            *(float2*)(g_ctx + (((size_t)n*BB + b)*SS + i)*HH + h*HD + d) = o;
        }
    }
}

// ---------------------------------------------------------------------------
// K5: output projection (tf32).  grid (6, 32, 3): z = n.
// ---------------------------------------------------------------------------
__global__ void __launch_bounds__(256) outproj_tc(
    const float* __restrict__ bo, float* __restrict__ out)
{
    __shared__ unsigned sA[128*32], sB[128*32];
    const int n = blockIdx.z;
    const float* X    = g_ctx + (size_t)n*MM*HH;
    const float* Wt   = g_wt + (size_t)(9+n)*HH*HH;
    const float* bias = bo + (size_t)n*HH;
    float* O = out + (size_t)n*MM*HH;

    const int m0 = blockIdx.y*128, e0 = blockIdx.x*128;
    const int tid = threadIdx.x, wid = tid>>5, lane = tid&31;
    const int gid = lane>>2, tig = lane&3;
    const int wm = wid & 1, wn = wid >> 1;

    float acc[4][4][4] = {};
    for(int k0=0;k0<HH;k0+=32){
        load_tile<128>(sA, X  + (size_t)m0*HH, HH, k0, tid);
        load_tile<128>(sB, Wt + (size_t)e0*HH, HH, k0, tid);
        __syncthreads();
        mma_block<4,4>(sA, sB, wm*64, wn*32, gid, tig, acc);
        __syncthreads();
    }
#pragma unroll
    for(int mi=0;mi<4;mi++)
#pragma unroll
    for(int ni=0;ni<4;ni++){
        const int e = e0 + wn*32 + ni*8 + 2*tig;
        const float2 b2 = *(const float2*)(bias + e);
#pragma unroll
        for(int h2=0;h2<2;h2++){
            int m = m0 + wm*64 + mi*16 + gid + h2*8;
            float2 o; o.x = acc[mi][ni][h2*2+0] + b2.x; o.y = acc[mi][ni][h2*2+1] + b2.y;
            *(float2*)(O + (size_t)m*HH + e) = o;
        }
    }
}

// ---------------------------------------------------------------------------
// Launch
// ---------------------------------------------------------------------------
extern "C" void kernel_launch(void* const* d_in, const int* in_sizes, int n_in,
                              void* d_out, int out_size)
{
    (void)in_sizes; (void)n_in; (void)out_size;
    const float* hidden = (const float*)d_in[0];
    // d_in[1] aspect_weights, d_in[2] opinion_weights: per-query-row biases cancel in softmax
    const int*   mask   = (const int*)  d_in[3];
    const float* Wq = (const float*)d_in[4];  const float* bq = (const float*)d_in[5];
    const float* Wk = (const float*)d_in[6];  const float* bk = (const float*)d_in[7];
    const float* Wv = (const float*)d_in[8];  const float* bv = (const float*)d_in[9];
    const float* Wo = (const float*)d_in[10]; const float* bo = (const float*)d_in[11];
    float* out = (float*)d_out;

    transpose_w<<<dim3(24,24,12), 256>>>(Wq, Wk, Wv, Wo);
    proj_tc    <<<dim3(6, 32, 9), 256>>>(hidden, bq, bk, bv);
    transpose_v<<<dim3(2, 64, 72), 256>>>();
    score_tc   <<<dim3(16, 16, 72), 256>>>(mask);
    softmax_all<<<dim3(BB*NHEAD*SS), 256>>>();
    ctx_tc     <<<dim3(16, 72), 256>>>();
    outproj_tc <<<dim3(6, 32, 3), 256>>>(bo, out);
}

// round 3
// speedup vs baseline: 3.2574x; 1.2088x over previous
#include <cuda_runtime.h>
#include <cstddef>

// Problem constants
#define BB 2
#define SS 2048
#define HH 768
#define NHEAD 12
#define HD 64
#define MM (BB*SS)          // 4096
#define SCALE 0.125f        // HD^-0.5

// ---------------------------------------------------------------------------
// Device scratch
// ---------------------------------------------------------------------------
__device__ float g_q [(size_t)3*BB*NHEAD*SS*HD];
__device__ float g_k [(size_t)3*BB*NHEAD*SS*HD];
__device__ float g_v [(size_t)3*BB*NHEAD*SS*HD];
__device__ float g_vt[(size_t)3*BB*NHEAD*SS*HD];     // V transposed: [n][bh][d][s]
__device__ float g_s0[(size_t)BB*NHEAD*SS*SS];
__device__ float g_s1[(size_t)BB*NHEAD*SS*SS];
__device__ float g_s2[(size_t)BB*NHEAD*SS*SS];
__device__ float g_ctx[(size_t)3*MM*HH];
__device__ float g_wt[(size_t)12*HH*HH];             // transposed weights: q0..2,k0..2,v0..2,o0..2

// ---------------------------------------------------------------------------
// tf32 mma helpers
// ---------------------------------------------------------------------------
__device__ __forceinline__ unsigned f2tf(float x){
    unsigned r; asm("cvt.rna.tf32.f32 %0, %1;" : "=r"(r) : "f"(x)); return r;
}
__device__ __forceinline__ void mma8(float c[4], const unsigned a[4], const unsigned b[2]){
    asm volatile("mma.sync.aligned.m16n8k8.row.col.f32.tf32.tf32.f32 "
        "{%0,%1,%2,%3},{%4,%5,%6,%7},{%8,%9},{%0,%1,%2,%3};"
        : "+f"(c[0]),"+f"(c[1]),"+f"(c[2]),"+f"(c[3])
        : "r"(a[0]),"r"(a[1]),"r"(a[2]),"r"(a[3]),"r"(b[0]),"r"(b[1]));
}
// smem tile: rows of 32 floats, float4-group XOR swizzle (bank-conflict free).
__device__ __forceinline__ int swz(int row, int c){ return (row<<5) + ((c ^ (row & 7))<<2); }

// cp.async 16B
__device__ __forceinline__ void cp16(float* s, const float* g){
    unsigned sa = (unsigned)__cvta_generic_to_shared(s);
    asm volatile("cp.async.cg.shared.global [%0], [%1], 16;" :: "r"(sa), "l"(g));
}
#define CP_COMMIT()   asm volatile("cp.async.commit_group;")
#define CP_WAIT(N)    asm volatile("cp.async.wait_group %0;" :: "n"(N))

// Async load of a [ROWS x 32] k-major tile (row stride ld) into swizzled smem (raw fp32).
template<int ROWS>
__device__ __forceinline__ void load_tile_async(float* s, const float* __restrict__ g,
                                                size_t ld, int k0, int tid){
#pragma unroll
    for(int i=0;i<ROWS*8/256;i++){
        int idx = i*256 + tid;
        int row = idx>>3, c = idx&7;
        cp16(s + swz(row,c), g + (size_t)row*ld + k0 + 4*c);
    }
}

// One BK=32 block-step: warp tile = MI m16-tiles x NI n8-tiles. tf32 cvt at load.
template<int MI,int NI>
__device__ __forceinline__ void mma_block(const float* sA, const float* sB,
        int wm_base, int wn_base, int gid, int tig, float acc[MI][NI][4]){
#pragma unroll
    for(int ks=0;ks<4;ks++){
        unsigned af[MI][4], bf[NI][2];
#pragma unroll
        for(int mi=0;mi<MI;mi++){
            int m = wm_base + mi*16 + gid;
            af[mi][0] = f2tf(sA[swz(m,   2*ks  )+tig]);
            af[mi][1] = f2tf(sA[swz(m+8, 2*ks  )+tig]);
            af[mi][2] = f2tf(sA[swz(m,   2*ks+1)+tig]);
            af[mi][3] = f2tf(sA[swz(m+8, 2*ks+1)+tig]);
        }
#pragma unroll
        for(int ni=0;ni<NI;ni++){
            int n = wn_base + ni*8 + gid;
            bf[ni][0] = f2tf(sB[swz(n, 2*ks  )+tig]);
            bf[ni][1] = f2tf(sB[swz(n, 2*ks+1)+tig]);
        }
#pragma unroll
        for(int mi=0;mi<MI;mi++)
#pragma unroll
            for(int ni=0;ni<NI;ni++)
                mma8(acc[mi][ni], af[mi], bf[ni]);
    }
}

// ---------------------------------------------------------------------------
// K0a: transpose the 12 weight matrices [h][e] -> g_wt[mat][e][h]
// ---------------------------------------------------------------------------
__global__ void __launch_bounds__(256) transpose_w(
    const float* __restrict__ Wq, const float* __restrict__ Wk,
    const float* __restrict__ Wv, const float* __restrict__ Wo)
{
    __shared__ float t[32][33];
    const int mat = blockIdx.z;
    const float* src = (mat<3?Wq:mat<6?Wk:mat<9?Wv:Wo) + (size_t)(mat%3)*HH*HH;
    float* dst = g_wt + (size_t)mat*HH*HH;
    const int x0 = blockIdx.x*32, y0 = blockIdx.y*32;
    const int tx = threadIdx.x & 31, ty = threadIdx.x >> 5;  // 32 x 8
#pragma unroll
    for(int r=0;r<4;r++) t[ty+8*r][tx] = src[(size_t)(y0+ty+8*r)*HH + x0 + tx];
    __syncthreads();
#pragma unroll
    for(int r=0;r<4;r++) dst[(size_t)(x0+ty+8*r)*HH + y0 + tx] = t[tx][ty+8*r];
}

// K1b: transpose V per head: [s][d] -> [d][s]
__global__ void __launch_bounds__(256) transpose_v()
{
    __shared__ float t[32][33];
    const int z = blockIdx.z;                   // n*24+bh
    const float* src = g_v  + (size_t)z*SS*HD;
    float* dst       = g_vt + (size_t)z*SS*HD;
    const int d0 = blockIdx.x*32, s0 = blockIdx.y*32;
    const int tx = threadIdx.x & 31, ty = threadIdx.x >> 5;
#pragma unroll
    for(int r=0;r<4;r++) t[ty+8*r][tx] = src[(size_t)(s0+ty+8*r)*HD + d0 + tx];
    __syncthreads();
#pragma unroll
    for(int r=0;r<4;r++) dst[(size_t)(d0+ty+8*r)*SS + s0 + tx] = t[tx][ty+8*r];
}

// ---------------------------------------------------------------------------
// Generic double-buffered GEMM body: C[128 x 64] tile, K = KTOT.
// A: [m][k] row stride lda,  B: [n][k] row stride ldb (both k-major).
// ---------------------------------------------------------------------------
template<int KTOT>
__device__ __forceinline__ void gemm_body(
    float* sA, float* sB,                       // sA: 2*128*32, sB: 2*64*32
    const float* __restrict__ A, size_t lda,
    const float* __restrict__ B, size_t ldb,
    int tid, int wm_base, int wn_base, int gid, int tig,
    float acc[4][2][4])
{
    load_tile_async<128>(sA, A, lda, 0, tid);
    load_tile_async<64 >(sB, B, ldb, 0, tid);
    CP_COMMIT();
    const int nk = KTOT/32;
#pragma unroll 1
    for(int kt=0; kt<nk; kt++){
        const int cur = kt & 1, nxt = cur ^ 1;
        if(kt+1 < nk){
            load_tile_async<128>(sA + nxt*128*32, A, lda, (kt+1)*32, tid);
            load_tile_async<64 >(sB + nxt*64*32,  B, ldb, (kt+1)*32, tid);
        }
        CP_COMMIT();
        CP_WAIT(1);
        __syncthreads();
        mma_block<4,2>(sA + cur*128*32, sB + cur*64*32, wm_base, wn_base, gid, tig, acc);
        __syncthreads();
    }
}

// ---------------------------------------------------------------------------
// K1: QKV projection (tf32).  grid (12, 32, 9): x=e-tile/64, y=m-tile/128, z=(t*3+n)
// ---------------------------------------------------------------------------
__global__ void __launch_bounds__(256,2) proj_tc(
    const float* __restrict__ X,
    const float* __restrict__ bq, const float* __restrict__ bk, const float* __restrict__ bv)
{
    __shared__ float sA[2*128*32], sB[2*64*32];
    const int z = blockIdx.z, n = z%3, t = z/3;
    const float* Wt   = g_wt + (size_t)(t*3+n)*HH*HH;
    const float* bias = (t==0?bq:(t==1?bk:bv)) + (size_t)n*HH;
    float* O = (t==0?g_q:(t==1?g_k:g_v)) + (size_t)n*BB*NHEAD*SS*HD;

    const int m0 = blockIdx.y*128, e0 = blockIdx.x*64;
    const int tid = threadIdx.x, wid = tid>>5, lane = tid&31;
    const int gid = lane>>2, tig = lane&3;
    const int wm = wid & 1, wn = wid >> 1;       // 2x4 warps; warp tile 64x16

    float acc[4][2][4] = {};
    gemm_body<HH>(sA, sB, X + (size_t)m0*HH, HH, Wt + (size_t)e0*HH, HH,
                  tid, wm*64, wn*16, gid, tig, acc);

#pragma unroll
    for(int mi=0;mi<4;mi++)
#pragma unroll
    for(int ni=0;ni<2;ni++){
        const int e = e0 + wn*16 + ni*8 + 2*tig;
        const float2 b2 = *(const float2*)(bias + e);
        const int head = e>>6, d = e&63;
#pragma unroll
        for(int h2=0;h2<2;h2++){
            int m = m0 + wm*64 + mi*16 + gid + h2*8;
            int b = m>>11, s = m & (SS-1);
            float2 o; o.x = acc[mi][ni][h2*2+0] + b2.x; o.y = acc[mi][ni][h2*2+1] + b2.y;
            *(float2*)(O + (((size_t)b*NHEAD + head)*SS + s)*HD + d) = o;
        }
    }
}

// ---------------------------------------------------------------------------
// K2: scores (tf32).  grid (32, 16, 72): x=j-tile/64, y=i-tile/128, z -> n,bh
// K=64 fully resident: single load phase, no k-loop.
// ---------------------------------------------------------------------------
__global__ void __launch_bounds__(256,2) score_tc(const int* __restrict__ mask)
{
    __shared__ float sQ[2*128*32], sK[2*64*32];
    const int z = blockIdx.z, n = z/24, bh = z%24, b = bh/NHEAD;
    const float* q = g_q + ((size_t)n*24 + bh)*SS*HD;
    const float* k = g_k + ((size_t)n*24 + bh)*SS*HD;
    float* sout = (n==0?g_s0:(n==1?g_s1:g_s2)) + (size_t)bh*SS*SS;

    const int i0 = blockIdx.y*128, j0 = blockIdx.x*64;
    const int tid = threadIdx.x, wid = tid>>5, lane = tid&31;
    const int gid = lane>>2, tig = lane&3;
    const int wm = wid & 1, wn = wid >> 1;

    load_tile_async<128>(sQ,          q + (size_t)i0*HD, HD,  0, tid);
    load_tile_async<128>(sQ + 128*32, q + (size_t)i0*HD, HD, 32, tid);
    load_tile_async<64 >(sK,          k + (size_t)j0*HD, HD,  0, tid);
    load_tile_async<64 >(sK + 64*32,  k + (size_t)j0*HD, HD, 32, tid);
    CP_COMMIT();
    CP_WAIT(0);
    __syncthreads();

    float acc[4][2][4] = {};
    mma_block<4,2>(sQ,          sK,         wm*64, wn*16, gid, tig, acc);
    mma_block<4,2>(sQ + 128*32, sK + 64*32, wm*64, wn*16, gid, tig, acc);

#pragma unroll
    for(int mi=0;mi<4;mi++)
#pragma unroll
    for(int ni=0;ni<2;ni++){
        const int j = j0 + wn*16 + ni*8 + 2*tig;
        const bool mk0 = (mask[b*SS + j    ] == 0);
        const bool mk1 = (mask[b*SS + j + 1] == 0);
#pragma unroll
        for(int h2=0;h2<2;h2++){
            int i = i0 + wm*64 + mi*16 + gid + h2*8;
            float2 o;
            o.x = mk0 ? -1e30f : acc[mi][ni][h2*2+0]*SCALE;
            o.y = mk1 ? -1e30f : acc[mi][ni][h2*2+1]*SCALE;
            *(float2*)(sout + (size_t)i*SS + j) = o;
        }
    }
}

// ---------------------------------------------------------------------------
// K3: merged softmax (unchanged; DRAM-bound)
// ---------------------------------------------------------------------------
__device__ __forceinline__ float warpMax(float v){
#pragma unroll
    for(int o=16;o;o>>=1) v = fmaxf(v, __shfl_xor_sync(0xffffffffu, v, o));
    return v;
}
__device__ __forceinline__ float warpSum(float v){
#pragma unroll
    for(int o=16;o;o>>=1) v += __shfl_xor_sync(0xffffffffu, v, o);
    return v;
}

__global__ void __launch_bounds__(256) softmax_all()
{
    const size_t row = (size_t)blockIdx.x * SS;
    float* p0 = g_s0 + row;
    float* p1 = g_s1 + row;
    float* p2 = g_s2 + row;
    const int tid = threadIdx.x, lane = tid&31, warp = tid>>5;

    float v0[8], v1[8], v2[8];
    *(float4*)(v0  ) = *(const float4*)(p0 + tid*8);
    *(float4*)(v0+4) = *(const float4*)(p0 + tid*8 + 4);
    *(float4*)(v1  ) = *(const float4*)(p1 + tid*8);
    *(float4*)(v1+4) = *(const float4*)(p1 + tid*8 + 4);
    *(float4*)(v2  ) = *(const float4*)(p2 + tid*8);
    *(float4*)(v2+4) = *(const float4*)(p2 + tid*8 + 4);

    __shared__ float rA[8], rB[8];
    __shared__ float bA, bB;

    float m0 = v0[0], m1 = v1[0];
#pragma unroll
    for(int i=1;i<8;i++){ m0 = fmaxf(m0, v0[i]); m1 = fmaxf(m1, v1[i]); }
    m0 = warpMax(m0); m1 = warpMax(m1);
    if(lane==0){ rA[warp]=m0; rB[warp]=m1; }
    __syncthreads();
    if(tid==0){ float a=rA[0], c=rB[0];
        for(int i=1;i<8;i++){ a=fmaxf(a,rA[i]); c=fmaxf(c,rB[i]); } bA=a; bB=c; }
    __syncthreads();
    const float M0=bA, M1=bB;

    float s0=0.f, s1=0.f;
#pragma unroll
    for(int i=0;i<8;i++){ v0[i]=__expf(v0[i]-M0); s0+=v0[i];
                          v1[i]=__expf(v1[i]-M1); s1+=v1[i]; }
    s0 = warpSum(s0); s1 = warpSum(s1);
    if(lane==0){ rA[warp]=s0; rB[warp]=s1; }
    __syncthreads();
    if(tid==0){ float a=0,c=0; for(int i=0;i<8;i++){a+=rA[i]; c+=rB[i];}
        bA=1.0f/a; bB=1.0f/c; }
    __syncthreads();
    const float inv0=bA, inv1=bB;

    float t[8];
#pragma unroll
    for(int i=0;i<8;i++){
        v0[i] *= inv0; v1[i] *= inv1;
        t[i] = v2[i] + 0.5f*(v0[i] + v1[i]);
    }
    *(float4*)(p0 + tid*8    ) = *(float4*)(v0  );
    *(float4*)(p0 + tid*8 + 4) = *(float4*)(v0+4);
    *(float4*)(p1 + tid*8    ) = *(float4*)(v1  );
    *(float4*)(p1 + tid*8 + 4) = *(float4*)(v1+4);

    float m2 = t[0];
#pragma unroll
    for(int i=1;i<8;i++) m2 = fmaxf(m2, t[i]);
    m2 = warpMax(m2);
    if(lane==0) rA[warp]=m2;
    __syncthreads();
    if(tid==0){ float a=rA[0]; for(int i=1;i<8;i++) a=fmaxf(a,rA[i]); bA=a; }
    __syncthreads();
    const float M2=bA;

    float s2=0.f;
#pragma unroll
    for(int i=0;i<8;i++){ t[i]=__expf(t[i]-M2); s2+=t[i]; }
    s2 = warpSum(s2);
    __syncthreads();
    if(lane==0) rA[warp]=s2;
    __syncthreads();
    if(tid==0){ float a=0; for(int i=0;i<8;i++) a+=rA[i]; bA=1.0f/a; }
    __syncthreads();
    const float inv2=bA;
#pragma unroll
    for(int i=0;i<8;i++) t[i]*=inv2;
    *(float4*)(p2 + tid*8    ) = *(float4*)(t  );
    *(float4*)(p2 + tid*8 + 4) = *(float4*)(t+4);
}

// ---------------------------------------------------------------------------
// K4: ctx = P @ V (tf32).  grid (16, 72). C tile 128(i) x 64(d), K=2048.
// ---------------------------------------------------------------------------
__global__ void __launch_bounds__(256,2) ctx_tc()
{
    __shared__ float sA[2*128*32], sB[2*64*32];
    const int z = blockIdx.y, n = z/24, bh = z%24, b = bh/NHEAD, h = bh%NHEAD;
    const float* P  = (n==0?g_s0:(n==1?g_s1:g_s2)) + (size_t)bh*SS*SS;
    const float* Vt = g_vt + ((size_t)n*24 + bh)*SS*HD;
    const int i0 = blockIdx.x*128;

    const int tid = threadIdx.x, wid = tid>>5, lane = tid&31;
    const int gid = lane>>2, tig = lane&3;
    const int wm = wid & 1, wn = wid >> 1;

    float acc[4][2][4] = {};
    gemm_body<SS>(sA, sB, P + (size_t)i0*SS, SS, Vt, SS,
                  tid, wm*64, wn*16, gid, tig, acc);

#pragma unroll
    for(int mi=0;mi<4;mi++)
#pragma unroll
    for(int ni=0;ni<2;ni++){
        const int d = wn*16 + ni*8 + 2*tig;
#pragma unroll
        for(int h2=0;h2<2;h2++){
            int i = i0 + wm*64 + mi*16 + gid + h2*8;
            float2 o; o.x = acc[mi][ni][h2*2+0]; o.y = acc[mi][ni][h2*2+1];
            *(float2*)(g_ctx + (((size_t)n*BB + b)*SS + i)*HH + h*HD + d) = o;
        }
    }
}

// ---------------------------------------------------------------------------
// K5: output projection (tf32).  grid (12, 32, 3): z = n.
// ---------------------------------------------------------------------------
__global__ void __launch_bounds__(256,2) outproj_tc(
    const float* __restrict__ bo, float* __restrict__ out)
{
    __shared__ float sA[2*128*32], sB[2*64*32];
    const int n = blockIdx.z;
    const float* X    = g_ctx + (size_t)n*MM*HH;
    const float* Wt   = g_wt + (size_t)(9+n)*HH*HH;
    const float* bias = bo + (size_t)n*HH;
    float* O = out + (size_t)n*MM*HH;

    const int m0 = blockIdx.y*128, e0 = blockIdx.x*64;
    const int tid = threadIdx.x, wid = tid>>5, lane = tid&31;
    const int gid = lane>>2, tig = lane&3;
    const int wm = wid & 1, wn = wid >> 1;

    float acc[4][2][4] = {};
    gemm_body<HH>(sA, sB, X + (size_t)m0*HH, HH, Wt + (size_t)e0*HH, HH,
                  tid, wm*64, wn*16, gid, tig, acc);

#pragma unroll
    for(int mi=0;mi<4;mi++)
#pragma unroll
    for(int ni=0;ni<2;ni++){
        const int e = e0 + wn*16 + ni*8 + 2*tig;
        const float2 b2 = *(const float2*)(bias + e);
#pragma unroll
        for(int h2=0;h2<2;h2++){
            int m = m0 + wm*64 + mi*16 + gid + h2*8;
            float2 o; o.x = acc[mi][ni][h2*2+0] + b2.x; o.y = acc[mi][ni][h2*2+1] + b2.y;
            *(float2*)(O + (size_t)m*HH + e) = o;
        }
    }
}

// ---------------------------------------------------------------------------
// Launch
// ---------------------------------------------------------------------------
extern "C" void kernel_launch(void* const* d_in, const int* in_sizes, int n_in,
                              void* d_out, int out_size)
{
    (void)in_sizes; (void)n_in; (void)out_size;
    const float* hidden = (const float*)d_in[0];
    // d_in[1] aspect_weights, d_in[2] opinion_weights: per-query-row biases cancel in softmax
    const int*   mask   = (const int*)  d_in[3];
    const float* Wq = (const float*)d_in[4];  const float* bq = (const float*)d_in[5];
    const float* Wk = (const float*)d_in[6];  const float* bk = (const float*)d_in[7];
    const float* Wv = (const float*)d_in[8];  const float* bv = (const float*)d_in[9];
    const float* Wo = (const float*)d_in[10]; const float* bo = (const float*)d_in[11];
    float* out = (float*)d_out;

    transpose_w<<<dim3(24,24,12), 256>>>(Wq, Wk, Wv, Wo);
    proj_tc    <<<dim3(12, 32, 9), 256>>>(hidden, bq, bk, bv);
    transpose_v<<<dim3(2, 64, 72), 256>>>();
    score_tc   <<<dim3(32, 16, 72), 256>>>(mask);
    softmax_all<<<dim3(BB*NHEAD*SS), 256>>>();
    ctx_tc     <<<dim3(16, 72), 256>>>();
    outproj_tc <<<dim3(12, 32, 3), 256>>>(bo, out);
}

// round 4
// speedup vs baseline: 3.5045x; 1.0759x over previous
#include <cuda_runtime.h>
#include <cstddef>

// Problem constants
#define BB 2
#define SS 2048
#define HH 768
#define NHEAD 12
#define HD 64
#define MM (BB*SS)          // 4096
#define SCALE 0.125f        // HD^-0.5

// ---------------------------------------------------------------------------
// Device scratch
// ---------------------------------------------------------------------------
__device__ float g_q [(size_t)3*BB*NHEAD*SS*HD];
__device__ float g_k [(size_t)3*BB*NHEAD*SS*HD];
__device__ float g_v [(size_t)3*BB*NHEAD*SS*HD];
__device__ float g_vt[(size_t)3*BB*NHEAD*SS*HD];     // V transposed: [n][bh][d][s]
__device__ float g_s0[(size_t)BB*NHEAD*SS*SS];
__device__ float g_s1[(size_t)BB*NHEAD*SS*SS];
__device__ float g_s2[(size_t)BB*NHEAD*SS*SS];
__device__ float g_ctx[(size_t)3*MM*HH];
__device__ float g_wt[(size_t)12*HH*HH];             // transposed + tf32-rounded weights

// ---------------------------------------------------------------------------
// tf32 helpers.  Pre-rounded fp32 values ARE valid tf32 mma operands when
// reloaded raw (__float_as_uint), so producers round and consumers skip cvt.
// ---------------------------------------------------------------------------
__device__ __forceinline__ unsigned f2tf(float x){
    unsigned r; asm("cvt.rna.tf32.f32 %0, %1;" : "=r"(r) : "f"(x)); return r;
}
__device__ __forceinline__ float f2tf_f(float x){ return __uint_as_float(f2tf(x)); }

__device__ __forceinline__ void mma8(float c[4], const unsigned a[4], const unsigned b[2]){
    asm volatile("mma.sync.aligned.m16n8k8.row.col.f32.tf32.tf32.f32 "
        "{%0,%1,%2,%3},{%4,%5,%6,%7},{%8,%9},{%0,%1,%2,%3};"
        : "+f"(c[0]),"+f"(c[1]),"+f"(c[2]),"+f"(c[3])
        : "r"(a[0]),"r"(a[1]),"r"(a[2]),"r"(a[3]),"r"(b[0]),"r"(b[1]));
}
// smem tile: rows of 32 floats, float4-group XOR swizzle (bank-conflict free).
__device__ __forceinline__ int swz(int row, int c){ return (row<<5) + ((c ^ (row & 7))<<2); }

// cp.async 16B
__device__ __forceinline__ void cp16(float* s, const float* g){
    unsigned sa = (unsigned)__cvta_generic_to_shared(s);
    asm volatile("cp.async.cg.shared.global [%0], [%1], 16;" :: "r"(sa), "l"(g));
}
#define CP_COMMIT()   asm volatile("cp.async.commit_group;")
#define CP_WAIT(N)    asm volatile("cp.async.wait_group %0;" :: "n"(N))

// Async load of a [ROWS x 32] k-major tile (row stride ld) into swizzled smem.
template<int ROWS>
__device__ __forceinline__ void load_tile_async(float* s, const float* __restrict__ g,
                                                size_t ld, int k0, int tid){
#pragma unroll
    for(int i=0;i<ROWS*8/256;i++){
        int idx = i*256 + tid;
        int row = idx>>3, c = idx&7;
        cp16(s + swz(row,c), g + (size_t)row*ld + k0 + 4*c);
    }
}

// One BK=32 block-step. CA/CB: convert fragment to tf32 at load (else data
// is pre-rounded and loaded raw).
template<int MI,int NI,bool CA,bool CB>
__device__ __forceinline__ void mma_block(const float* sA, const float* sB,
        int wm_base, int wn_base, int gid, int tig, float acc[MI][NI][4]){
#pragma unroll
    for(int ks=0;ks<4;ks++){
        unsigned af[MI][4], bf[NI][2];
#pragma unroll
        for(int mi=0;mi<MI;mi++){
            int m = wm_base + mi*16 + gid;
            float a0 = sA[swz(m,   2*ks  )+tig];
            float a1 = sA[swz(m+8, 2*ks  )+tig];
            float a2 = sA[swz(m,   2*ks+1)+tig];
            float a3 = sA[swz(m+8, 2*ks+1)+tig];
            af[mi][0] = CA ? f2tf(a0) : __float_as_uint(a0);
            af[mi][1] = CA ? f2tf(a1) : __float_as_uint(a1);
            af[mi][2] = CA ? f2tf(a2) : __float_as_uint(a2);
            af[mi][3] = CA ? f2tf(a3) : __float_as_uint(a3);
        }
#pragma unroll
        for(int ni=0;ni<NI;ni++){
            int n = wn_base + ni*8 + gid;
            float b0 = sB[swz(n, 2*ks  )+tig];
            float b1 = sB[swz(n, 2*ks+1)+tig];
            bf[ni][0] = CB ? f2tf(b0) : __float_as_uint(b0);
            bf[ni][1] = CB ? f2tf(b1) : __float_as_uint(b1);
        }
#pragma unroll
        for(int mi=0;mi<MI;mi++)
#pragma unroll
            for(int ni=0;ni<NI;ni++)
                mma8(acc[mi][ni], af[mi], bf[ni]);
    }
}

// ---------------------------------------------------------------------------
// K0a: transpose + tf32-round the 12 weight matrices [h][e] -> g_wt[mat][e][h]
// ---------------------------------------------------------------------------
__global__ void __launch_bounds__(256) transpose_w(
    const float* __restrict__ Wq, const float* __restrict__ Wk,
    const float* __restrict__ Wv, const float* __restrict__ Wo)
{
    __shared__ float t[32][33];
    const int mat = blockIdx.z;
    const float* src = (mat<3?Wq:mat<6?Wk:mat<9?Wv:Wo) + (size_t)(mat%3)*HH*HH;
    float* dst = g_wt + (size_t)mat*HH*HH;
    const int x0 = blockIdx.x*32, y0 = blockIdx.y*32;
    const int tx = threadIdx.x & 31, ty = threadIdx.x >> 5;  // 32 x 8
#pragma unroll
    for(int r=0;r<4;r++) t[ty+8*r][tx] = f2tf_f(src[(size_t)(y0+ty+8*r)*HH + x0 + tx]);
    __syncthreads();
#pragma unroll
    for(int r=0;r<4;r++) dst[(size_t)(x0+ty+8*r)*HH + y0 + tx] = t[tx][ty+8*r];
}

// K1b: transpose V per head: [s][d] -> [d][s]  (values already tf32-rounded)
__global__ void __launch_bounds__(256) transpose_v()
{
    __shared__ float t[32][33];
    const int z = blockIdx.z;                   // n*24+bh
    const float* src = g_v  + (size_t)z*SS*HD;
    float* dst       = g_vt + (size_t)z*SS*HD;
    const int d0 = blockIdx.x*32, s0 = blockIdx.y*32;
    const int tx = threadIdx.x & 31, ty = threadIdx.x >> 5;
#pragma unroll
    for(int r=0;r<4;r++) t[ty+8*r][tx] = src[(size_t)(s0+ty+8*r)*HD + d0 + tx];
    __syncthreads();
#pragma unroll
    for(int r=0;r<4;r++) dst[(size_t)(d0+ty+8*r)*SS + s0 + tx] = t[tx][ty+8*r];
}

// ---------------------------------------------------------------------------
// Generic double-buffered GEMM body: C[128 x 64] tile, K = KTOT.
// ---------------------------------------------------------------------------
template<int KTOT,bool CA,bool CB>
__device__ __forceinline__ void gemm_body(
    float* sA, float* sB,                       // sA: 2*128*32, sB: 2*64*32
    const float* __restrict__ A, size_t lda,
    const float* __restrict__ B, size_t ldb,
    int tid, int wm_base, int wn_base, int gid, int tig,
    float acc[4][2][4])
{
    load_tile_async<128>(sA, A, lda, 0, tid);
    load_tile_async<64 >(sB, B, ldb, 0, tid);
    CP_COMMIT();
    const int nk = KTOT/32;
#pragma unroll 1
    for(int kt=0; kt<nk; kt++){
        const int cur = kt & 1, nxt = cur ^ 1;
        if(kt+1 < nk){
            load_tile_async<128>(sA + nxt*128*32, A, lda, (kt+1)*32, tid);
            load_tile_async<64 >(sB + nxt*64*32,  B, ldb, (kt+1)*32, tid);
        }
        CP_COMMIT();
        CP_WAIT(1);
        __syncthreads();
        mma_block<4,2,CA,CB>(sA + cur*128*32, sB + cur*64*32, wm_base, wn_base, gid, tig, acc);
        __syncthreads();
    }
}

// ---------------------------------------------------------------------------
// K1: QKV projection.  grid (12, 32, 9). A=hidden (cvt), B=g_wt (pre-rounded).
// Writes q/k/v tf32-rounded.
// ---------------------------------------------------------------------------
__global__ void __launch_bounds__(256,3) proj_tc(
    const float* __restrict__ X,
    const float* __restrict__ bq, const float* __restrict__ bk, const float* __restrict__ bv)
{
    __shared__ float sA[2*128*32], sB[2*64*32];
    const int z = blockIdx.z, n = z%3, t = z/3;
    const float* Wt   = g_wt + (size_t)(t*3+n)*HH*HH;
    const float* bias = (t==0?bq:(t==1?bk:bv)) + (size_t)n*HH;
    float* O = (t==0?g_q:(t==1?g_k:g_v)) + (size_t)n*BB*NHEAD*SS*HD;

    const int m0 = blockIdx.y*128, e0 = blockIdx.x*64;
    const int tid = threadIdx.x, wid = tid>>5, lane = tid&31;
    const int gid = lane>>2, tig = lane&3;
    const int wm = wid & 1, wn = wid >> 1;       // 2x4 warps; warp tile 64x16

    float acc[4][2][4] = {};
    gemm_body<HH,true,false>(sA, sB, X + (size_t)m0*HH, HH, Wt + (size_t)e0*HH, HH,
                             tid, wm*64, wn*16, gid, tig, acc);

#pragma unroll
    for(int mi=0;mi<4;mi++)
#pragma unroll
    for(int ni=0;ni<2;ni++){
        const int e = e0 + wn*16 + ni*8 + 2*tig;
        const float2 b2 = *(const float2*)(bias + e);
        const int head = e>>6, d = e&63;
#pragma unroll
        for(int h2=0;h2<2;h2++){
            int m = m0 + wm*64 + mi*16 + gid + h2*8;
            int b = m>>11, s = m & (SS-1);
            float2 o;
            o.x = f2tf_f(acc[mi][ni][h2*2+0] + b2.x);
            o.y = f2tf_f(acc[mi][ni][h2*2+1] + b2.y);
            *(float2*)(O + (((size_t)b*NHEAD + head)*SS + s)*HD + d) = o;
        }
    }
}

// ---------------------------------------------------------------------------
// K2: scores.  grid (32, 16, 72). Inputs pre-rounded: no cvt in inner loop.
// ---------------------------------------------------------------------------
__global__ void __launch_bounds__(256,3) score_tc(const int* __restrict__ mask)
{
    __shared__ float sQ[2*128*32], sK[2*64*32];
    const int z = blockIdx.z, n = z/24, bh = z%24, b = bh/NHEAD;
    const float* q = g_q + ((size_t)n*24 + bh)*SS*HD;
    const float* k = g_k + ((size_t)n*24 + bh)*SS*HD;
    float* sout = (n==0?g_s0:(n==1?g_s1:g_s2)) + (size_t)bh*SS*SS;

    const int i0 = blockIdx.y*128, j0 = blockIdx.x*64;
    const int tid = threadIdx.x, wid = tid>>5, lane = tid&31;
    const int gid = lane>>2, tig = lane&3;
    const int wm = wid & 1, wn = wid >> 1;

    load_tile_async<128>(sQ,          q + (size_t)i0*HD, HD,  0, tid);
    load_tile_async<128>(sQ + 128*32, q + (size_t)i0*HD, HD, 32, tid);
    load_tile_async<64 >(sK,          k + (size_t)j0*HD, HD,  0, tid);
    load_tile_async<64 >(sK + 64*32,  k + (size_t)j0*HD, HD, 32, tid);
    CP_COMMIT();
    CP_WAIT(0);
    __syncthreads();

    float acc[4][2][4] = {};
    mma_block<4,2,false,false>(sQ,          sK,         wm*64, wn*16, gid, tig, acc);
    mma_block<4,2,false,false>(sQ + 128*32, sK + 64*32, wm*64, wn*16, gid, tig, acc);

#pragma unroll
    for(int mi=0;mi<4;mi++)
#pragma unroll
    for(int ni=0;ni<2;ni++){
        const int j = j0 + wn*16 + ni*8 + 2*tig;
        const bool mk0 = (mask[b*SS + j    ] == 0);
        const bool mk1 = (mask[b*SS + j + 1] == 0);
#pragma unroll
        for(int h2=0;h2<2;h2++){
            int i = i0 + wm*64 + mi*16 + gid + h2*8;
            float2 o;
            o.x = mk0 ? -1e30f : acc[mi][ni][h2*2+0]*SCALE;
            o.y = mk1 ? -1e30f : acc[mi][ni][h2*2+1]*SCALE;
            *(float2*)(sout + (size_t)i*SS + j) = o;
        }
    }
}

// ---------------------------------------------------------------------------
// K3: merged softmax.  Writes p0/p1/p2 tf32-rounded (consumed as mma A).
// ---------------------------------------------------------------------------
__device__ __forceinline__ float warpMax(float v){
#pragma unroll
    for(int o=16;o;o>>=1) v = fmaxf(v, __shfl_xor_sync(0xffffffffu, v, o));
    return v;
}
__device__ __forceinline__ float warpSum(float v){
#pragma unroll
    for(int o=16;o;o>>=1) v += __shfl_xor_sync(0xffffffffu, v, o);
    return v;
}

__global__ void __launch_bounds__(256) softmax_all()
{
    const size_t row = (size_t)blockIdx.x * SS;
    float* p0 = g_s0 + row;
    float* p1 = g_s1 + row;
    float* p2 = g_s2 + row;
    const int tid = threadIdx.x, lane = tid&31, warp = tid>>5;

    float v0[8], v1[8], v2[8];
    *(float4*)(v0  ) = *(const float4*)(p0 + tid*8);
    *(float4*)(v0+4) = *(const float4*)(p0 + tid*8 + 4);
    *(float4*)(v1  ) = *(const float4*)(p1 + tid*8);
    *(float4*)(v1+4) = *(const float4*)(p1 + tid*8 + 4);
    *(float4*)(v2  ) = *(const float4*)(p2 + tid*8);
    *(float4*)(v2+4) = *(const float4*)(p2 + tid*8 + 4);

    __shared__ float rA[8], rB[8];
    __shared__ float bA, bB;

    float m0 = v0[0], m1 = v1[0];
#pragma unroll
    for(int i=1;i<8;i++){ m0 = fmaxf(m0, v0[i]); m1 = fmaxf(m1, v1[i]); }
    m0 = warpMax(m0); m1 = warpMax(m1);
    if(lane==0){ rA[warp]=m0; rB[warp]=m1; }
    __syncthreads();
    if(tid==0){ float a=rA[0], c=rB[0];
        for(int i=1;i<8;i++){ a=fmaxf(a,rA[i]); c=fmaxf(c,rB[i]); } bA=a; bB=c; }
    __syncthreads();
    const float M0=bA, M1=bB;

    float s0=0.f, s1=0.f;
#pragma unroll
    for(int i=0;i<8;i++){ v0[i]=__expf(v0[i]-M0); s0+=v0[i];
                          v1[i]=__expf(v1[i]-M1); s1+=v1[i]; }
    s0 = warpSum(s0); s1 = warpSum(s1);
    if(lane==0){ rA[warp]=s0; rB[warp]=s1; }
    __syncthreads();
    if(tid==0){ float a=0,c=0; for(int i=0;i<8;i++){a+=rA[i]; c+=rB[i];}
        bA=1.0f/a; bB=1.0f/c; }
    __syncthreads();
    const float inv0=bA, inv1=bB;

    float t[8];
#pragma unroll
    for(int i=0;i<8;i++){
        v0[i] *= inv0; v1[i] *= inv1;
        t[i] = v2[i] + 0.5f*(v0[i] + v1[i]);
    }
    float w0[8], w1[8];
#pragma unroll
    for(int i=0;i<8;i++){ w0[i]=f2tf_f(v0[i]); w1[i]=f2tf_f(v1[i]); }
    *(float4*)(p0 + tid*8    ) = *(float4*)(w0  );
    *(float4*)(p0 + tid*8 + 4) = *(float4*)(w0+4);
    *(float4*)(p1 + tid*8    ) = *(float4*)(w1  );
    *(float4*)(p1 + tid*8 + 4) = *(float4*)(w1+4);

    float m2 = t[0];
#pragma unroll
    for(int i=1;i<8;i++) m2 = fmaxf(m2, t[i]);
    m2 = warpMax(m2);
    if(lane==0) rA[warp]=m2;
    __syncthreads();
    if(tid==0){ float a=rA[0]; for(int i=1;i<8;i++) a=fmaxf(a,rA[i]); bA=a; }
    __syncthreads();
    const float M2=bA;

    float s2=0.f;
#pragma unroll
    for(int i=0;i<8;i++){ t[i]=__expf(t[i]-M2); s2+=t[i]; }
    s2 = warpSum(s2);
    __syncthreads();
    if(lane==0) rA[warp]=s2;
    __syncthreads();
    if(tid==0){ float a=0; for(int i=0;i<8;i++) a+=rA[i]; bA=1.0f/a; }
    __syncthreads();
    const float inv2=bA;
#pragma unroll
    for(int i=0;i<8;i++) t[i]=f2tf_f(t[i]*inv2);
    *(float4*)(p2 + tid*8    ) = *(float4*)(t  );
    *(float4*)(p2 + tid*8 + 4) = *(float4*)(t+4);
}

// ---------------------------------------------------------------------------
// K4: ctx = P @ V.  grid (16, 72). Inputs pre-rounded: no cvt.
// Writes g_ctx tf32-rounded (consumed as mma A by outproj).
// ---------------------------------------------------------------------------
__global__ void __launch_bounds__(256,3) ctx_tc()
{
    __shared__ float sA[2*128*32], sB[2*64*32];
    const int z = blockIdx.y, n = z/24, bh = z%24, b = bh/NHEAD, h = bh%NHEAD;
    const float* P  = (n==0?g_s0:(n==1?g_s1:g_s2)) + (size_t)bh*SS*SS;
    const float* Vt = g_vt + ((size_t)n*24 + bh)*SS*HD;
    const int i0 = blockIdx.x*128;

    const int tid = threadIdx.x, wid = tid>>5, lane = tid&31;
    const int gid = lane>>2, tig = lane&3;
    const int wm = wid & 1, wn = wid >> 1;

    float acc[4][2][4] = {};
    gemm_body<SS,false,false>(sA, sB, P + (size_t)i0*SS, SS, Vt, SS,
                              tid, wm*64, wn*16, gid, tig, acc);

#pragma unroll
    for(int mi=0;mi<4;mi++)
#pragma unroll
    for(int ni=0;ni<2;ni++){
        const int d = wn*16 + ni*8 + 2*tig;
#pragma unroll
        for(int h2=0;h2<2;h2++){
            int i = i0 + wm*64 + mi*16 + gid + h2*8;
            float2 o;
            o.x = f2tf_f(acc[mi][ni][h2*2+0]);
            o.y = f2tf_f(acc[mi][ni][h2*2+1]);
            *(float2*)(g_ctx + (((size_t)n*BB + b)*SS + i)*HH + h*HD + d) = o;
        }
    }
}

// ---------------------------------------------------------------------------
// K5: output projection.  grid (12, 32, 3). Both operands pre-rounded.
// ---------------------------------------------------------------------------
__global__ void __launch_bounds__(256,3) outproj_tc(
    const float* __restrict__ bo, float* __restrict__ out)
{
    __shared__ float sA[2*128*32], sB[2*64*32];
    const int n = blockIdx.z;
    const float* X    = g_ctx + (size_t)n*MM*HH;
    const float* Wt   = g_wt + (size_t)(9+n)*HH*HH;
    const float* bias = bo + (size_t)n*HH;
    float* O = out + (size_t)n*MM*HH;

    const int m0 = blockIdx.y*128, e0 = blockIdx.x*64;
    const int tid = threadIdx.x, wid = tid>>5, lane = tid&31;
    const int gid = lane>>2, tig = lane&3;
    const int wm = wid & 1, wn = wid >> 1;

    float acc[4][2][4] = {};
    gemm_body<HH,false,false>(sA, sB, X + (size_t)m0*HH, HH, Wt + (size_t)e0*HH, HH,
                              tid, wm*64, wn*16, gid, tig, acc);

#pragma unroll
    for(int mi=0;mi<4;mi++)
#pragma unroll
    for(int ni=0;ni<2;ni++){
        const int e = e0 + wn*16 + ni*8 + 2*tig;
        const float2 b2 = *(const float2*)(bias + e);
#pragma unroll
        for(int h2=0;h2<2;h2++){
            int m = m0 + wm*64 + mi*16 + gid + h2*8;
            float2 o; o.x = acc[mi][ni][h2*2+0] + b2.x; o.y = acc[mi][ni][h2*2+1] + b2.y;
            *(float2*)(O + (size_t)m*HH + e) = o;
        }
    }
}

// ---------------------------------------------------------------------------
// Launch
// ---------------------------------------------------------------------------
extern "C" void kernel_launch(void* const* d_in, const int* in_sizes, int n_in,
                              void* d_out, int out_size)
{
    (void)in_sizes; (void)n_in; (void)out_size;
    const float* hidden = (const float*)d_in[0];
    // d_in[1] aspect_weights, d_in[2] opinion_weights: per-query-row biases cancel in softmax
    const int*   mask   = (const int*)  d_in[3];
    const float* Wq = (const float*)d_in[4];  const float* bq = (const float*)d_in[5];
    const float* Wk = (const float*)d_in[6];  const float* bk = (const float*)d_in[7];
    const float* Wv = (const float*)d_in[8];  const float* bv = (const float*)d_in[9];
    const float* Wo = (const float*)d_in[10]; const float* bo = (const float*)d_in[11];
    float* out = (float*)d_out;

    transpose_w<<<dim3(24,24,12), 256>>>(Wq, Wk, Wv, Wo);
    proj_tc    <<<dim3(12, 32, 9), 256>>>(hidden, bq, bk, bv);
    transpose_v<<<dim3(2, 64, 72), 256>>>();
    score_tc   <<<dim3(32, 16, 72), 256>>>(mask);
    softmax_all<<<dim3(BB*NHEAD*SS), 256>>>();
    ctx_tc     <<<dim3(16, 72), 256>>>();
    outproj_tc <<<dim3(12, 32, 3), 256>>>(bo, out);
}

// round 5
// speedup vs baseline: 3.9561x; 1.1289x over previous
#include <cuda_runtime.h>
#include <cstddef>

// Problem constants
#define BB 2
#define SS 2048
#define HH 768
#define NHEAD 12
#define HD 64
#define MM (BB*SS)          // 4096
#define SCALE 0.125f        // HD^-0.5

// ---------------------------------------------------------------------------
// Device scratch
// ---------------------------------------------------------------------------
__device__ float g_q [(size_t)3*BB*NHEAD*SS*HD];
__device__ float g_k [(size_t)3*BB*NHEAD*SS*HD];
__device__ float g_v [(size_t)3*BB*NHEAD*SS*HD];
__device__ float g_vt[(size_t)3*BB*NHEAD*SS*HD];     // V transposed: [n][bh][d][s]
__device__ float g_s0[(size_t)BB*NHEAD*SS*SS];
__device__ float g_s1[(size_t)BB*NHEAD*SS*SS];
__device__ float g_s2[(size_t)BB*NHEAD*SS*SS];
__device__ float g_ctx[(size_t)3*MM*HH];
__device__ float g_wt[(size_t)12*HH*HH];             // transposed + tf32-rounded weights

// ---------------------------------------------------------------------------
// tf32 helpers.  Pre-rounded fp32 values ARE valid tf32 mma operands when
// reloaded raw, so producers round and consumers skip cvt.
// ---------------------------------------------------------------------------
__device__ __forceinline__ unsigned f2tf(float x){
    unsigned r; asm("cvt.rna.tf32.f32 %0, %1;" : "=r"(r) : "f"(x)); return r;
}
__device__ __forceinline__ float f2tf_f(float x){ return __uint_as_float(f2tf(x)); }

__device__ __forceinline__ void mma8(float c[4], const unsigned a[4], const unsigned b[2]){
    asm volatile("mma.sync.aligned.m16n8k8.row.col.f32.tf32.tf32.f32 "
        "{%0,%1,%2,%3},{%4,%5,%6,%7},{%8,%9},{%0,%1,%2,%3};"
        : "+f"(c[0]),"+f"(c[1]),"+f"(c[2]),"+f"(c[3])
        : "r"(a[0]),"r"(a[1]),"r"(a[2]),"r"(a[3]),"r"(b[0]),"r"(b[1]));
}
// smem tile: rows of 32 floats, float4-group XOR swizzle (bank-conflict free).
__device__ __forceinline__ int swz(int row, int c){ return (row<<5) + ((c ^ (row & 7))<<2); }

// cp.async 16B
__device__ __forceinline__ void cp16(float* s, const float* g){
    unsigned sa = (unsigned)__cvta_generic_to_shared(s);
    asm volatile("cp.async.cg.shared.global [%0], [%1], 16;" :: "r"(sa), "l"(g));
}
#define CP_COMMIT()   asm volatile("cp.async.commit_group;")
#define CP_WAIT(N)    asm volatile("cp.async.wait_group %0;" :: "n"(N))

// Async load of a [ROWS x 32] k-major tile (row stride ld) into swizzled smem.
template<int ROWS>
__device__ __forceinline__ void load_tile_async(float* s, const float* __restrict__ g,
                                                size_t ld, int k0, int tid){
#pragma unroll
    for(int i=0;i<ROWS*8/256;i++){
        int idx = i*256 + tid;
        int row = idx>>3, c = idx&7;
        cp16(s + swz(row,c), g + (size_t)row*ld + k0 + 4*c);
    }
}

// One BK=32 block-step. Warp tile = MI m16 x NI n8. CA/CB: cvt at load.
template<int MI,int NI,bool CA,bool CB>
__device__ __forceinline__ void mma_block(const float* sA, const float* sB,
        int wm_base, int wn_base, int gid, int tig, float acc[MI][NI][4]){
#pragma unroll
    for(int ks=0;ks<4;ks++){
        unsigned af[MI][4], bf[NI][2];
#pragma unroll
        for(int mi=0;mi<MI;mi++){
            int m = wm_base + mi*16 + gid;
            float a0 = sA[swz(m,   2*ks  )+tig];
            float a1 = sA[swz(m+8, 2*ks  )+tig];
            float a2 = sA[swz(m,   2*ks+1)+tig];
            float a3 = sA[swz(m+8, 2*ks+1)+tig];
            af[mi][0] = CA ? f2tf(a0) : __float_as_uint(a0);
            af[mi][1] = CA ? f2tf(a1) : __float_as_uint(a1);
            af[mi][2] = CA ? f2tf(a2) : __float_as_uint(a2);
            af[mi][3] = CA ? f2tf(a3) : __float_as_uint(a3);
        }
#pragma unroll
        for(int ni=0;ni<NI;ni++){
            int n = wn_base + ni*8 + gid;
            float b0 = sB[swz(n, 2*ks  )+tig];
            float b1 = sB[swz(n, 2*ks+1)+tig];
            bf[ni][0] = CB ? f2tf(b0) : __float_as_uint(b0);
            bf[ni][1] = CB ? f2tf(b1) : __float_as_uint(b1);
        }
#pragma unroll
        for(int mi=0;mi<MI;mi++)
#pragma unroll
            for(int ni=0;ni<NI;ni++)
                mma8(acc[mi][ni], af[mi], bf[ni]);
    }
}

// ---------------------------------------------------------------------------
// K0a: transpose + tf32-round the 12 weight matrices [h][e] -> g_wt[mat][e][h]
// ---------------------------------------------------------------------------
__global__ void __launch_bounds__(256) transpose_w(
    const float* __restrict__ Wq, const float* __restrict__ Wk,
    const float* __restrict__ Wv, const float* __restrict__ Wo)
{
    __shared__ float t[32][33];
    const int mat = blockIdx.z;
    const float* src = (mat<3?Wq:mat<6?Wk:mat<9?Wv:Wo) + (size_t)(mat%3)*HH*HH;
    float* dst = g_wt + (size_t)mat*HH*HH;
    const int x0 = blockIdx.x*32, y0 = blockIdx.y*32;
    const int tx = threadIdx.x & 31, ty = threadIdx.x >> 5;  // 32 x 8
#pragma unroll
    for(int r=0;r<4;r++) t[ty+8*r][tx] = f2tf_f(src[(size_t)(y0+ty+8*r)*HH + x0 + tx]);
    __syncthreads();
#pragma unroll
    for(int r=0;r<4;r++) dst[(size_t)(x0+ty+8*r)*HH + y0 + tx] = t[tx][ty+8*r];
}

// K1b: transpose V per head: [s][d] -> [d][s]  (values already tf32-rounded)
__global__ void __launch_bounds__(256) transpose_v()
{
    __shared__ float t[32][33];
    const int z = blockIdx.z;                   // n*24+bh
    const float* src = g_v  + (size_t)z*SS*HD;
    float* dst       = g_vt + (size_t)z*SS*HD;
    const int d0 = blockIdx.x*32, s0 = blockIdx.y*32;
    const int tx = threadIdx.x & 31, ty = threadIdx.x >> 5;
#pragma unroll
    for(int r=0;r<4;r++) t[ty+8*r][tx] = src[(size_t)(s0+ty+8*r)*HD + d0 + tx];
    __syncthreads();
#pragma unroll
    for(int r=0;r<4;r++) dst[(size_t)(d0+ty+8*r)*SS + s0 + tx] = t[tx][ty+8*r];
}

// ---------------------------------------------------------------------------
// Generic double-buffered GEMM body: C[AR x BR] tile, K = KTOT, MI=NI=4.
// ---------------------------------------------------------------------------
template<int KTOT,int AR,int BR,bool CA,bool CB>
__device__ __forceinline__ void gemm_body(
    float* sA, float* sB,                       // sA: 2*AR*32, sB: 2*BR*32
    const float* __restrict__ A, size_t lda,
    const float* __restrict__ B, size_t ldb,
    int tid, int wm_base, int wn_base, int gid, int tig,
    float acc[4][4][4])
{
    load_tile_async<AR>(sA, A, lda, 0, tid);
    load_tile_async<BR>(sB, B, ldb, 0, tid);
    CP_COMMIT();
    const int nk = KTOT/32;
#pragma unroll 1
    for(int kt=0; kt<nk; kt++){
        const int cur = kt & 1, nxt = cur ^ 1;
        if(kt+1 < nk){
            load_tile_async<AR>(sA + nxt*AR*32, A, lda, (kt+1)*32, tid);
            load_tile_async<BR>(sB + nxt*BR*32, B, ldb, (kt+1)*32, tid);
        }
        CP_COMMIT();
        CP_WAIT(1);
        __syncthreads();
        mma_block<4,4,CA,CB>(sA + cur*AR*32, sB + cur*BR*32, wm_base, wn_base, gid, tig, acc);
        __syncthreads();
    }
}

// ---------------------------------------------------------------------------
// K1: QKV projection.  Block 128x128. grid (6, 32, 9).
// A=hidden (cvt at load), B=g_wt (pre-rounded). Writes q/k/v tf32-rounded.
// ---------------------------------------------------------------------------
__global__ void __launch_bounds__(256,2) proj_tc(
    const float* __restrict__ X,
    const float* __restrict__ bq, const float* __restrict__ bk, const float* __restrict__ bv)
{
    extern __shared__ float sm[];
    float* sA = sm;             // 2*128*32
    float* sB = sm + 2*128*32;  // 2*128*32
    const int z = blockIdx.z, n = z%3, t = z/3;
    const float* Wt   = g_wt + (size_t)(t*3+n)*HH*HH;
    const float* bias = (t==0?bq:(t==1?bk:bv)) + (size_t)n*HH;
    float* O = (t==0?g_q:(t==1?g_k:g_v)) + (size_t)n*BB*NHEAD*SS*HD;

    const int m0 = blockIdx.y*128, e0 = blockIdx.x*128;
    const int tid = threadIdx.x, wid = tid>>5, lane = tid&31;
    const int gid = lane>>2, tig = lane&3;
    const int wm = wid & 1, wn = wid >> 1;       // 2x4 warps; warp tile 64x32

    float acc[4][4][4] = {};
    gemm_body<HH,128,128,true,false>(sA, sB, X + (size_t)m0*HH, HH, Wt + (size_t)e0*HH, HH,
                                     tid, wm*64, wn*32, gid, tig, acc);

#pragma unroll
    for(int mi=0;mi<4;mi++)
#pragma unroll
    for(int ni=0;ni<4;ni++){
        const int e = e0 + wn*32 + ni*8 + 2*tig;
        const float2 b2 = *(const float2*)(bias + e);
        const int head = e>>6, d = e&63;
#pragma unroll
        for(int h2=0;h2<2;h2++){
            int m = m0 + wm*64 + mi*16 + gid + h2*8;
            int b = m>>11, s = m & (SS-1);
            float2 o;
            o.x = f2tf_f(acc[mi][ni][h2*2+0] + b2.x);
            o.y = f2tf_f(acc[mi][ni][h2*2+1] + b2.y);
            *(float2*)(O + (((size_t)b*NHEAD + head)*SS + s)*HD + d) = o;
        }
    }
}

// ---------------------------------------------------------------------------
// K2: scores.  Block 128x128, K=64 fully resident. grid (16, 16, 72).
// ---------------------------------------------------------------------------
__global__ void __launch_bounds__(256,2) score_tc(const int* __restrict__ mask)
{
    extern __shared__ float sm[];
    float* sQ = sm;             // 2 k-subtiles of 128x32
    float* sK = sm + 2*128*32;
    const int z = blockIdx.z, n = z/24, bh = z%24, b = bh/NHEAD;
    const float* q = g_q + ((size_t)n*24 + bh)*SS*HD;
    const float* k = g_k + ((size_t)n*24 + bh)*SS*HD;
    float* sout = (n==0?g_s0:(n==1?g_s1:g_s2)) + (size_t)bh*SS*SS;

    const int i0 = blockIdx.y*128, j0 = blockIdx.x*128;
    const int tid = threadIdx.x, wid = tid>>5, lane = tid&31;
    const int gid = lane>>2, tig = lane&3;
    const int wm = wid & 1, wn = wid >> 1;

    load_tile_async<128>(sQ,          q + (size_t)i0*HD, HD,  0, tid);
    load_tile_async<128>(sQ + 128*32, q + (size_t)i0*HD, HD, 32, tid);
    load_tile_async<128>(sK,          k + (size_t)j0*HD, HD,  0, tid);
    load_tile_async<128>(sK + 128*32, k + (size_t)j0*HD, HD, 32, tid);
    CP_COMMIT();
    CP_WAIT(0);
    __syncthreads();

    float acc[4][4][4] = {};
    mma_block<4,4,false,false>(sQ,          sK,          wm*64, wn*32, gid, tig, acc);
    mma_block<4,4,false,false>(sQ + 128*32, sK + 128*32, wm*64, wn*32, gid, tig, acc);

#pragma unroll
    for(int mi=0;mi<4;mi++)
#pragma unroll
    for(int ni=0;ni<4;ni++){
        const int j = j0 + wn*32 + ni*8 + 2*tig;
        const bool mk0 = (mask[b*SS + j    ] == 0);
        const bool mk1 = (mask[b*SS + j + 1] == 0);
#pragma unroll
        for(int h2=0;h2<2;h2++){
            int i = i0 + wm*64 + mi*16 + gid + h2*8;
            float2 o;
            o.x = mk0 ? -1e30f : acc[mi][ni][h2*2+0]*SCALE;
            o.y = mk1 ? -1e30f : acc[mi][ni][h2*2+1]*SCALE;
            *(float2*)(sout + (size_t)i*SS + j) = o;
        }
    }
}

// ---------------------------------------------------------------------------
// K3: merged softmax.  Writes p0/p1/p2 tf32-rounded (consumed as mma A).
// ---------------------------------------------------------------------------
__device__ __forceinline__ float warpMax(float v){
#pragma unroll
    for(int o=16;o;o>>=1) v = fmaxf(v, __shfl_xor_sync(0xffffffffu, v, o));
    return v;
}
__device__ __forceinline__ float warpSum(float v){
#pragma unroll
    for(int o=16;o;o>>=1) v += __shfl_xor_sync(0xffffffffu, v, o);
    return v;
}

__global__ void __launch_bounds__(256) softmax_all()
{
    const size_t row = (size_t)blockIdx.x * SS;
    float* p0 = g_s0 + row;
    float* p1 = g_s1 + row;
    float* p2 = g_s2 + row;
    const int tid = threadIdx.x, lane = tid&31, warp = tid>>5;

    float v0[8], v1[8], v2[8];
    *(float4*)(v0  ) = *(const float4*)(p0 + tid*8);
    *(float4*)(v0+4) = *(const float4*)(p0 + tid*8 + 4);
    *(float4*)(v1  ) = *(const float4*)(p1 + tid*8);
    *(float4*)(v1+4) = *(const float4*)(p1 + tid*8 + 4);
    *(float4*)(v2  ) = *(const float4*)(p2 + tid*8);
    *(float4*)(v2+4) = *(const float4*)(p2 + tid*8 + 4);

    __shared__ float rA[8], rB[8];
    __shared__ float bA, bB;

    float m0 = v0[0], m1 = v1[0];
#pragma unroll
    for(int i=1;i<8;i++){ m0 = fmaxf(m0, v0[i]); m1 = fmaxf(m1, v1[i]); }
    m0 = warpMax(m0); m1 = warpMax(m1);
    if(lane==0){ rA[warp]=m0; rB[warp]=m1; }
    __syncthreads();
    if(tid==0){ float a=rA[0], c=rB[0];
        for(int i=1;i<8;i++){ a=fmaxf(a,rA[i]); c=fmaxf(c,rB[i]); } bA=a; bB=c; }
    __syncthreads();
    const float M0=bA, M1=bB;

    float s0=0.f, s1=0.f;
#pragma unroll
    for(int i=0;i<8;i++){ v0[i]=__expf(v0[i]-M0); s0+=v0[i];
                          v1[i]=__expf(v1[i]-M1); s1+=v1[i]; }
    s0 = warpSum(s0); s1 = warpSum(s1);
    if(lane==0){ rA[warp]=s0; rB[warp]=s1; }
    __syncthreads();
    if(tid==0){ float a=0,c=0; for(int i=0;i<8;i++){a+=rA[i]; c+=rB[i];}
        bA=1.0f/a; bB=1.0f/c; }
    __syncthreads();
    const float inv0=bA, inv1=bB;

    float t[8];
#pragma unroll
    for(int i=0;i<8;i++){
        v0[i] *= inv0; v1[i] *= inv1;
        t[i] = v2[i] + 0.5f*(v0[i] + v1[i]);
    }
    float w0[8], w1[8];
#pragma unroll
    for(int i=0;i<8;i++){ w0[i]=f2tf_f(v0[i]); w1[i]=f2tf_f(v1[i]); }
    *(float4*)(p0 + tid*8    ) = *(float4*)(w0  );
    *(float4*)(p0 + tid*8 + 4) = *(float4*)(w0+4);
    *(float4*)(p1 + tid*8    ) = *(float4*)(w1  );
    *(float4*)(p1 + tid*8 + 4) = *(float4*)(w1+4);

    float m2 = t[0];
#pragma unroll
    for(int i=1;i<8;i++) m2 = fmaxf(m2, t[i]);
    m2 = warpMax(m2);
    if(lane==0) rA[warp]=m2;
    __syncthreads();
    if(tid==0){ float a=rA[0]; for(int i=1;i<8;i++) a=fmaxf(a,rA[i]); bA=a; }
    __syncthreads();
    const float M2=bA;

    float s2=0.f;
#pragma unroll
    for(int i=0;i<8;i++){ t[i]=__expf(t[i]-M2); s2+=t[i]; }
    s2 = warpSum(s2);
    __syncthreads();
    if(lane==0) rA[warp]=s2;
    __syncthreads();
    if(tid==0){ float a=0; for(int i=0;i<8;i++) a+=rA[i]; bA=1.0f/a; }
    __syncthreads();
    const float inv2=bA;
#pragma unroll
    for(int i=0;i<8;i++) t[i]=f2tf_f(t[i]*inv2);
    *(float4*)(p2 + tid*8    ) = *(float4*)(t  );
    *(float4*)(p2 + tid*8 + 4) = *(float4*)(t+4);
}

// ---------------------------------------------------------------------------
// K4: ctx = P @ V.  Block 256x64, warps 4m x 2n. grid (8, 72). K=2048.
// Writes g_ctx tf32-rounded (consumed as mma A by outproj).
// ---------------------------------------------------------------------------
__global__ void __launch_bounds__(256,2) ctx_tc()
{
    extern __shared__ float sm[];
    float* sA = sm;             // 2*256*32
    float* sB = sm + 2*256*32;  // 2*64*32
    const int z = blockIdx.y, n = z/24, bh = z%24, b = bh/NHEAD, h = bh%NHEAD;
    const float* P  = (n==0?g_s0:(n==1?g_s1:g_s2)) + (size_t)bh*SS*SS;
    const float* Vt = g_vt + ((size_t)n*24 + bh)*SS*HD;
    const int i0 = blockIdx.x*256;

    const int tid = threadIdx.x, wid = tid>>5, lane = tid&31;
    const int gid = lane>>2, tig = lane&3;
    const int wm = wid & 3, wn = wid >> 2;   // 4x2 warps; warp tile 64x32

    float acc[4][4][4] = {};
    gemm_body<SS,256,64,false,false>(sA, sB, P + (size_t)i0*SS, SS, Vt, SS,
                                     tid, wm*64, wn*32, gid, tig, acc);

#pragma unroll
    for(int mi=0;mi<4;mi++)
#pragma unroll
    for(int ni=0;ni<4;ni++){
        const int d = wn*32 + ni*8 + 2*tig;
#pragma unroll
        for(int h2=0;h2<2;h2++){
            int i = i0 + wm*64 + mi*16 + gid + h2*8;
            float2 o;
            o.x = f2tf_f(acc[mi][ni][h2*2+0]);
            o.y = f2tf_f(acc[mi][ni][h2*2+1]);
            *(float2*)(g_ctx + (((size_t)n*BB + b)*SS + i)*HH + h*HD + d) = o;
        }
    }
}

// ---------------------------------------------------------------------------
// K5: output projection.  Block 128x128. grid (6, 32, 3).
// ---------------------------------------------------------------------------
__global__ void __launch_bounds__(256,2) outproj_tc(
    const float* __restrict__ bo, float* __restrict__ out)
{
    extern __shared__ float sm[];
    float* sA = sm;
    float* sB = sm + 2*128*32;
    const int n = blockIdx.z;
    const float* X    = g_ctx + (size_t)n*MM*HH;
    const float* Wt   = g_wt + (size_t)(9+n)*HH*HH;
    const float* bias = bo + (size_t)n*HH;
    float* O = out + (size_t)n*MM*HH;

    const int m0 = blockIdx.y*128, e0 = blockIdx.x*128;
    const int tid = threadIdx.x, wid = tid>>5, lane = tid&31;
    const int gid = lane>>2, tig = lane&3;
    const int wm = wid & 1, wn = wid >> 1;

    float acc[4][4][4] = {};
    gemm_body<HH,128,128,false,false>(sA, sB, X + (size_t)m0*HH, HH, Wt + (size_t)e0*HH, HH,
                                      tid, wm*64, wn*32, gid, tig, acc);

#pragma unroll
    for(int mi=0;mi<4;mi++)
#pragma unroll
    for(int ni=0;ni<4;ni++){
        const int e = e0 + wn*32 + ni*8 + 2*tig;
        const float2 b2 = *(const float2*)(bias + e);
#pragma unroll
        for(int h2=0;h2<2;h2++){
            int m = m0 + wm*64 + mi*16 + gid + h2*8;
            float2 o; o.x = acc[mi][ni][h2*2+0] + b2.x; o.y = acc[mi][ni][h2*2+1] + b2.y;
            *(float2*)(O + (size_t)m*HH + e) = o;
        }
    }
}

// ---------------------------------------------------------------------------
// Launch
// ---------------------------------------------------------------------------
extern "C" void kernel_launch(void* const* d_in, const int* in_sizes, int n_in,
                              void* d_out, int out_size)
{
    (void)in_sizes; (void)n_in; (void)out_size;
    const float* hidden = (const float*)d_in[0];
    // d_in[1] aspect_weights, d_in[2] opinion_weights: per-query-row biases cancel in softmax
    const int*   mask   = (const int*)  d_in[3];
    const float* Wq = (const float*)d_in[4];  const float* bq = (const float*)d_in[5];
    const float* Wk = (const float*)d_in[6];  const float* bk = (const float*)d_in[7];
    const float* Wv = (const float*)d_in[8];  const float* bv = (const float*)d_in[9];
    const float* Wo = (const float*)d_in[10]; const float* bo = (const float*)d_in[11];
    float* out = (float*)d_out;

    const int smemAB  = (2*128*32 + 2*128*32) * 4;   // 64 KB
    const int smemCtx = (2*256*32 + 2*64*32) * 4;    // 80 KB
    cudaFuncSetAttribute(proj_tc,    cudaFuncAttributeMaxDynamicSharedMemorySize, smemAB);
    cudaFuncSetAttribute(score_tc,   cudaFuncAttributeMaxDynamicSharedMemorySize, smemAB);
    cudaFuncSetAttribute(ctx_tc,     cudaFuncAttributeMaxDynamicSharedMemorySize, smemCtx);
    cudaFuncSetAttribute(outproj_tc, cudaFuncAttributeMaxDynamicSharedMemorySize, smemAB);

    transpose_w<<<dim3(24,24,12), 256>>>(Wq, Wk, Wv, Wo);
    proj_tc    <<<dim3(6, 32, 9), 256, smemAB>>>(hidden, bq, bk, bv);
    transpose_v<<<dim3(2, 64, 72), 256>>>();
    score_tc   <<<dim3(16, 16, 72), 256, smemAB>>>(mask);
    softmax_all<<<dim3(BB*NHEAD*SS), 256>>>();
    ctx_tc     <<<dim3(8, 72), 256, smemCtx>>>();
    outproj_tc <<<dim3(6, 32, 3), 256, smemAB>>>(bo, out);
}